// round 1
// baseline (speedup 1.0000x reference)
#include <cuda_runtime.h>
#include <math.h>

#define D    2048
#define NH   32
#define HD   64
#define TT   256
#define NB   16
#define SK   512
#define BT   (NB*TT)   // 4096

#define OFF_K (BT*D)                  // 8388608
#define NKV   (NB*NH*SK*HD)           // 16777216
#define OFF_V (OFF_K + NKV)

// ---------------- scratch (device globals; no allocation allowed) ----------
__device__ float g_q[NB*NH*TT*HD];     // rotated Q, (B,H,T,Hd)
__device__ float g_katt[NB*NH*SK*HD];  // attention K (past tail + rotated cur)
__device__ float g_oattn[BT*D];        // attention out in (B,T,D)

// ---------------- GEMM: C[m,n] = sum_k A[m,k]*B[n,k]  (both row-major, K=D) --
#define BM 128
#define BN 128
#define BK 16

// mode 0: C row-major (ldc = D).
// mode 1: scatter to (B,H,S,Hd): dst = ((b*NH+h)*S + s0 + t)*HD + d
__global__ __launch_bounds__(256, 2)
void sgemm_nt(const float* __restrict__ A, const float* __restrict__ Bm,
              float* __restrict__ C, int mode, int S, int s0)
{
    __shared__ float As[2][BK][BM + 4];
    __shared__ float Bs[2][BK][BN + 4];

    const int tid = threadIdx.x;
    const int m0 = blockIdx.y * BM;
    const int n0 = blockIdx.x * BN;

    const int lr = tid >> 2;          // 0..63
    const int lc = (tid & 3) * 4;     // 0,4,8,12

    const float* Ag = A  + (size_t)(m0 + lr) * D + lc;
    const float* Bg = Bm + (size_t)(n0 + lr) * D + lc;

    float4 ra0, ra1, rb0, rb1;

    ra0 = *(const float4*)(Ag);
    ra1 = *(const float4*)(Ag + 64 * D);
    rb0 = *(const float4*)(Bg);
    rb1 = *(const float4*)(Bg + 64 * D);

    {
        float a0[4] = {ra0.x, ra0.y, ra0.z, ra0.w};
        float a1[4] = {ra1.x, ra1.y, ra1.z, ra1.w};
        float b0[4] = {rb0.x, rb0.y, rb0.z, rb0.w};
        float b1[4] = {rb1.x, rb1.y, rb1.z, rb1.w};
        #pragma unroll
        for (int i = 0; i < 4; ++i) {
            As[0][lc + i][lr]      = a0[i];
            As[0][lc + i][lr + 64] = a1[i];
            Bs[0][lc + i][lr]      = b0[i];
            Bs[0][lc + i][lr + 64] = b1[i];
        }
    }
    __syncthreads();

    const int ty = tid >> 4;   // 0..15
    const int tx = tid & 15;   // 0..15

    float acc[8][8];
    #pragma unroll
    for (int i = 0; i < 8; ++i)
        #pragma unroll
        for (int j = 0; j < 8; ++j) acc[i][j] = 0.f;

    const int nk = D / BK;  // 128
    int buf = 0;
    for (int kt = 0; kt < nk; ++kt) {
        if (kt + 1 < nk) {
            const float* Ap = Ag + (kt + 1) * BK;
            const float* Bp = Bg + (kt + 1) * BK;
            ra0 = *(const float4*)(Ap);
            ra1 = *(const float4*)(Ap + 64 * D);
            rb0 = *(const float4*)(Bp);
            rb1 = *(const float4*)(Bp + 64 * D);
        }
        #pragma unroll
        for (int kk = 0; kk < BK; ++kk) {
            float4 a0 = *(const float4*)&As[buf][kk][ty * 8];
            float4 a1 = *(const float4*)&As[buf][kk][ty * 8 + 4];
            float4 b0 = *(const float4*)&Bs[buf][kk][tx * 8];
            float4 b1 = *(const float4*)&Bs[buf][kk][tx * 8 + 4];
            float a[8] = {a0.x, a0.y, a0.z, a0.w, a1.x, a1.y, a1.z, a1.w};
            float b[8] = {b0.x, b0.y, b0.z, b0.w, b1.x, b1.y, b1.z, b1.w};
            #pragma unroll
            for (int i = 0; i < 8; ++i)
                #pragma unroll
                for (int j = 0; j < 8; ++j)
                    acc[i][j] += a[i] * b[j];
        }
        if (kt + 1 < nk) {
            int nb = buf ^ 1;
            float a0[4] = {ra0.x, ra0.y, ra0.z, ra0.w};
            float a1[4] = {ra1.x, ra1.y, ra1.z, ra1.w};
            float b0[4] = {rb0.x, rb0.y, rb0.z, rb0.w};
            float b1[4] = {rb1.x, rb1.y, rb1.z, rb1.w};
            #pragma unroll
            for (int i = 0; i < 4; ++i) {
                As[nb][lc + i][lr]      = a0[i];
                As[nb][lc + i][lr + 64] = a1[i];
                Bs[nb][lc + i][lr]      = b0[i];
                Bs[nb][lc + i][lr + 64] = b1[i];
            }
            __syncthreads();
            buf = nb;
        }
    }

    // epilogue
    const int mb = m0 + ty * 8;
    const int nb_ = n0 + tx * 8;
    if (mode == 0) {
        #pragma unroll
        for (int i = 0; i < 8; ++i) {
            float* dst = C + (size_t)(mb + i) * D + nb_;
            float4 o0 = {acc[i][0], acc[i][1], acc[i][2], acc[i][3]};
            float4 o1 = {acc[i][4], acc[i][5], acc[i][6], acc[i][7]};
            *(float4*)(dst)     = o0;
            *(float4*)(dst + 4) = o1;
        }
    } else {
        const int h = nb_ >> 6;
        const int d = nb_ & 63;
        #pragma unroll
        for (int i = 0; i < 8; ++i) {
            int m = mb + i;
            int b = m >> 8;      // /TT
            int t = m & 255;     // %TT
            float* dst = C + ((size_t)((b * NH + h) * S + s0 + t)) * HD + d;
            float4 o0 = {acc[i][0], acc[i][1], acc[i][2], acc[i][3]};
            float4 o1 = {acc[i][4], acc[i][5], acc[i][6], acc[i][7]};
            *(float4*)(dst)     = o0;
            *(float4*)(dst + 4) = o1;
        }
    }
}

// ---------------- prep: cache tail copies + RoPE --------------------------
// one thread per (bh, s, pair j) ; s in [0,512), j in [0,32)
__global__ void prep_kernel(const float* __restrict__ past_k,
                            const float* __restrict__ past_v,
                            float* __restrict__ new_k,
                            float* __restrict__ new_v,
                            float* __restrict__ q,       // in-place rope
                            float* __restrict__ katt,
                            const int* __restrict__ pos_ptr)
{
    int idx = blockIdx.x * blockDim.x + threadIdx.x;   // < 512*512*32 = 8388608
    int j  = idx & 31;
    int s  = (idx >> 5) & 511;
    int bh = idx >> 14;

    if (s < 256) {
        size_t src = ((size_t)bh * SK + (s + 256)) * HD + j * 2;
        size_t dst = ((size_t)bh * SK + s) * HD + j * 2;
        float2 kp = *(const float2*)(past_k + src);
        float2 vp = *(const float2*)(past_v + src);
        *(float2*)(new_k + dst) = kp;
        *(float2*)(katt + dst)  = kp;
        *(float2*)(new_v + dst) = vp;
    } else {
        int t = s - 256;
        float pos = (float)(pos_ptr[0] + t);
        // inv_freq = 10000^(-j/32) = exp2(-j * log2(10000)/32)
        float inv = exp2f(-(float)j * 0.41524101186091403f);
        float ang = pos * inv;
        float sn, cs;
        sincosf(ang, &sn, &cs);

        size_t dk = ((size_t)bh * SK + s) * HD + j * 2;
        float2 kv = *(const float2*)(new_k + dk);
        float2 kr = {kv.x * cs - kv.y * sn, kv.x * sn + kv.y * cs};
        *(float2*)(katt + dk) = kr;

        size_t dq = ((size_t)bh * TT + t) * HD + j * 2;
        float2 qv = *(const float2*)(q + dq);
        float2 qr = {qv.x * cs - qv.y * sn, qv.x * sn + qv.y * cs};
        *(float2*)(q + dq) = qr;
    }
}

// ---------------- attention: flash-style, 64 queries x 32-key chunks ------
__global__ __launch_bounds__(128)
void attn_kernel(const float* __restrict__ Q,    // (BH, 256, 64) rotated
                 const float* __restrict__ K,    // (BH, 512, 64)
                 const float* __restrict__ V,    // (BH, 512, 64)
                 float* __restrict__ O)          // (B, T, D)
{
    __shared__ float Qs[64 * 64];
    __shared__ float Ks[32 * 64];
    __shared__ float Vs[32 * 64];
    __shared__ float Ps[64 * 33];

    const int bh = blockIdx.y;
    const int q0 = blockIdx.x * 64;
    const int tid = threadIdx.x;       // 128
    const int tr = tid >> 3;           // 0..15  -> 4 query rows
    const int tc = tid & 7;            // 0..7   -> 4 score cols / 8 out cols

    const float scale = 0.125f;        // 1/sqrt(64)

    // load Q tile (pre-scaled), xor-swizzled by 16B column
    const float* Qg = Q + ((size_t)bh * TT + q0) * HD;
    for (int i = tid; i < 64 * 16; i += 128) {
        int r = i >> 4, c4 = i & 15;
        float4 v = *(const float4*)(Qg + r * 64 + c4 * 4);
        v.x *= scale; v.y *= scale; v.z *= scale; v.w *= scale;
        int p = c4 ^ ((r >> 2) & 7);
        *(float4*)&Qs[r * 64 + p * 4] = v;
    }

    float mrow[4], lrow[4], acc[4][8];
    #pragma unroll
    for (int i = 0; i < 4; ++i) {
        mrow[i] = -1e30f; lrow[i] = 0.f;
        #pragma unroll
        for (int j = 0; j < 8; ++j) acc[i][j] = 0.f;
    }

    const int nchunk = min(16, ((q0 + 319) >> 5) + 1);
    const float* Kg = K + (size_t)bh * SK * HD;
    const float* Vg = V + (size_t)bh * SK * HD;

    for (int c = 0; c < nchunk; ++c) {
        __syncthreads();
        // load 32x64 K,V chunk (swizzled)
        for (int i = tid; i < 512; i += 128) {
            int r = i >> 4, c4 = i & 15;
            int p = c4 ^ ((r >> 2) & 7);
            const float* kp = Kg + (c * 32 + r) * 64 + c4 * 4;
            const float* vp = Vg + (c * 32 + r) * 64 + c4 * 4;
            *(float4*)&Ks[r * 64 + p * 4] = *(const float4*)kp;
            *(float4*)&Vs[r * 64 + p * 4] = *(const float4*)vp;
        }
        __syncthreads();

        // S = Qtile @ Kchunk^T  (thread: 4q x 4k)
        float Sv[4][4];
        #pragma unroll
        for (int i = 0; i < 4; ++i)
            #pragma unroll
            for (int j = 0; j < 4; ++j) Sv[i][j] = 0.f;

        #pragma unroll
        for (int d4 = 0; d4 < 16; ++d4) {
            float4 a[4];
            int pq = (d4 ^ (tr & 7)) * 4;
            #pragma unroll
            for (int i = 0; i < 4; ++i)
                a[i] = *(const float4*)&Qs[(tr * 4 + i) * 64 + pq];
            int pk = (d4 ^ tc) * 4;
            #pragma unroll
            for (int j = 0; j < 4; ++j) {
                float4 b = *(const float4*)&Ks[(tc * 4 + j) * 64 + pk];
                #pragma unroll
                for (int i = 0; i < 4; ++i)
                    Sv[i][j] += a[i].x * b.x + a[i].y * b.y + a[i].z * b.z + a[i].w * b.w;
            }
        }

        // causal mask: key s visible iff s <= t + 256
        #pragma unroll
        for (int i = 0; i < 4; ++i) {
            int t = q0 + tr * 4 + i;
            #pragma unroll
            for (int j = 0; j < 4; ++j) {
                int s = c * 32 + tc * 4 + j;
                if (s > t + 256) Sv[i][j] = -1e30f;
            }
        }

        // row max (4 local + allreduce over 8 tc lanes)
        float mn[4];
        #pragma unroll
        for (int i = 0; i < 4; ++i)
            mn[i] = fmaxf(fmaxf(Sv[i][0], Sv[i][1]), fmaxf(Sv[i][2], Sv[i][3]));
        #pragma unroll
        for (int o = 1; o < 8; o <<= 1)
            #pragma unroll
            for (int i = 0; i < 4; ++i)
                mn[i] = fmaxf(mn[i], __shfl_xor_sync(0xffffffffu, mn[i], o));

        float rs[4];
        #pragma unroll
        for (int i = 0; i < 4; ++i) {
            float mN = fmaxf(mrow[i], mn[i]);
            float sc = __expf(mrow[i] - mN);
            mrow[i] = mN;
            float r = 0.f;
            #pragma unroll
            for (int j = 0; j < 4; ++j) {
                float p = __expf(Sv[i][j] - mN);
                Sv[i][j] = p;
                r += p;
            }
            rs[i] = r;
            lrow[i] *= sc;
            #pragma unroll
            for (int j = 0; j < 8; ++j) acc[i][j] *= sc;
        }
        #pragma unroll
        for (int o = 1; o < 8; o <<= 1)
            #pragma unroll
            for (int i = 0; i < 4; ++i)
                rs[i] += __shfl_xor_sync(0xffffffffu, rs[i], o);
        #pragma unroll
        for (int i = 0; i < 4; ++i) lrow[i] += rs[i];

        // stage P
        #pragma unroll
        for (int i = 0; i < 4; ++i)
            #pragma unroll
            for (int j = 0; j < 4; ++j)
                Ps[(tr * 4 + i) * 33 + tc * 4 + j] = Sv[i][j];
        __syncthreads();

        // O += P @ Vchunk   (thread: 4q x 8d)
        #pragma unroll 4
        for (int k = 0; k < 32; ++k) {
            int sw = (k >> 2) & 7;
            float4 v0 = *(const float4*)&Vs[k * 64 + ((tc * 2)     ^ sw) * 4];
            float4 v1 = *(const float4*)&Vs[k * 64 + ((tc * 2 + 1) ^ sw) * 4];
            float pp[4];
            #pragma unroll
            for (int i = 0; i < 4; ++i) pp[i] = Ps[(tr * 4 + i) * 33 + k];
            #pragma unroll
            for (int i = 0; i < 4; ++i) {
                acc[i][0] += pp[i] * v0.x; acc[i][1] += pp[i] * v0.y;
                acc[i][2] += pp[i] * v0.z; acc[i][3] += pp[i] * v0.w;
                acc[i][4] += pp[i] * v1.x; acc[i][5] += pp[i] * v1.y;
                acc[i][6] += pp[i] * v1.z; acc[i][7] += pp[i] * v1.w;
            }
        }
    }

    // write O in (B,T,D) layout
    const int b = bh >> 5;
    const int h = bh & 31;
    #pragma unroll
    for (int i = 0; i < 4; ++i) {
        float inv = 1.0f / lrow[i];
        int t = q0 + tr * 4 + i;
        float* dst = O + ((size_t)(b * TT + t)) * D + h * HD + tc * 8;
        float4 o0 = {acc[i][0] * inv, acc[i][1] * inv, acc[i][2] * inv, acc[i][3] * inv};
        float4 o1 = {acc[i][4] * inv, acc[i][5] * inv, acc[i][6] * inv, acc[i][7] * inv};
        *(float4*)(dst)     = o0;
        *(float4*)(dst + 4) = o1;
    }
}

// ---------------- launch ---------------------------------------------------
extern "C" void kernel_launch(void* const* d_in, const int* in_sizes, int n_in,
                              void* d_out, int out_size)
{
    const float* x      = (const float*)d_in[0];
    const float* past_k = (const float*)d_in[1];
    const float* past_v = (const float*)d_in[2];
    const float* Wq     = (const float*)d_in[3];
    const float* Wk     = (const float*)d_in[4];
    const float* Wv     = (const float*)d_in[5];
    const float* Wo     = (const float*)d_in[6];
    const int*   pos    = (const int*)d_in[7];

    float* out   = (float*)d_out;
    float* new_k = out + OFF_K;
    float* new_v = out + OFF_V;

    float *q_ptr, *katt_ptr, *oattn_ptr;
    cudaGetSymbolAddress((void**)&q_ptr,     g_q);
    cudaGetSymbolAddress((void**)&katt_ptr,  g_katt);
    cudaGetSymbolAddress((void**)&oattn_ptr, g_oattn);

    dim3 ggrid(D / BN, BT / BM);   // (16, 32)

    // Q/K/V projections with scatter epilogues
    sgemm_nt<<<ggrid, 256>>>(x, Wq, q_ptr, 1, TT, 0);
    sgemm_nt<<<ggrid, 256>>>(x, Wk, new_k, 1, SK, 256);
    sgemm_nt<<<ggrid, 256>>>(x, Wv, new_v, 1, SK, 256);

    // cache-tail copies + RoPE (q in place, k -> g_katt)
    prep_kernel<<<(NB * NH * SK * 32) / 256, 256>>>(past_k, past_v, new_k, new_v,
                                                    q_ptr, katt_ptr, pos);

    // attention
    attn_kernel<<<dim3(TT / 64, NB * NH), 128>>>(q_ptr, katt_ptr, new_v, oattn_ptr);

    // output projection
    sgemm_nt<<<ggrid, 256>>>(oattn_ptr, Wo, out, 0, 0, 0);

    (void)in_sizes; (void)n_in; (void)out_size;
}

// round 6
// speedup vs baseline: 2.2249x; 2.2249x over previous
#include <cuda_runtime.h>
#include <cuda_bf16.h>
#include <cstdint>
#include <math.h>

#define D    2048
#define NH   32
#define HD   64
#define TT   256
#define NB   16
#define SK   512
#define BT   (NB*TT)   // 4096

#define OFF_K (BT*D)
#define NKV   (NB*NH*SK*HD)
#define OFF_V (OFF_K + NKV)

// ---------------- scratch (device globals; no allocation allowed) ----------
__device__ float g_q[NB*NH*TT*HD];     // rotated Q, (B,H,T,Hd)
__device__ float g_katt[NB*NH*SK*HD];  // attention K
__device__ float g_oattn[BT*D];        // attention out (B,T,D)

__device__ __nv_bfloat16 g_xh[BT*D], g_xl[BT*D];     // split x
__device__ __nv_bfloat16 g_oh[BT*D], g_ol[BT*D];     // split oattn
__device__ __nv_bfloat16 g_wh[4][D*D], g_wl[4][D*D]; // split Wq,Wk,Wv,Wo

// ---------------- helpers ---------------------------------------------------
__device__ __forceinline__ uint32_t smem_u32(const void* p) {
    uint32_t a;
    asm("{ .reg .u64 t; cvta.to.shared.u64 t, %1; cvt.u32.u64 %0, t; }" : "=r"(a) : "l"(p));
    return a;
}
__device__ __forceinline__ void cp16(uint32_t dst, const void* src) {
    asm volatile("cp.async.cg.shared.global [%0], [%1], 16;" :: "r"(dst), "l"(src));
}
#define CP_COMMIT() asm volatile("cp.async.commit_group;" ::: "memory")

__device__ __forceinline__ void ldm_x4(uint32_t* r, uint32_t addr) {
    asm volatile("ldmatrix.sync.aligned.m8n8.x4.shared.b16 {%0,%1,%2,%3}, [%4];"
        : "=r"(r[0]), "=r"(r[1]), "=r"(r[2]), "=r"(r[3]) : "r"(addr));
}
__device__ __forceinline__ void mma_bf16(float* c, const uint32_t* a, const uint32_t* b) {
    asm volatile(
        "mma.sync.aligned.m16n8k16.row.col.f32.bf16.bf16.f32 "
        "{%0,%1,%2,%3}, {%4,%5,%6,%7}, {%8,%9}, {%0,%1,%2,%3};"
        : "+f"(c[0]), "+f"(c[1]), "+f"(c[2]), "+f"(c[3])
        : "r"(a[0]), "r"(a[1]), "r"(a[2]), "r"(a[3]), "r"(b[0]), "r"(b[1]));
}

// smem tile: 128 rows x 32 bf16 (64B rows, 4 x 16B units), xor swizzle
__device__ __forceinline__ uint32_t swoff(int r, int g) {
    return (uint32_t)(r * 64 + ((g ^ ((r >> 1) & 3)) * 16));
}

#define TILE_B   8192                 // 128 x 64B
#define STAGE_B  (4 * TILE_B)         // Ah | Al | Bh | Bl
#define NSTAGE   3
#define GEMM_SMEM (NSTAGE * STAGE_B)  // 98304

// ---------------- split: fp32 -> bf16 hi + bf16 lo --------------------------
__global__ void split_kernel(const float4* __restrict__ src,
                             ushort4* __restrict__ hi, ushort4* __restrict__ lo, int n4)
{
    int i = blockIdx.x * blockDim.x + threadIdx.x;
    if (i >= n4) return;
    float4 v = src[i];
    float f[4] = {v.x, v.y, v.z, v.w};
    unsigned short h[4], l[4];
    #pragma unroll
    for (int j = 0; j < 4; ++j) {
        __nv_bfloat16 hb = __float2bfloat16(f[j]);
        float hf = __bfloat162float(hb);
        __nv_bfloat16 lb = __float2bfloat16(f[j] - hf);
        h[j] = *reinterpret_cast<unsigned short*>(&hb);
        l[j] = *reinterpret_cast<unsigned short*>(&lb);
    }
    hi[i] = make_ushort4(h[0], h[1], h[2], h[3]);
    lo[i] = make_ushort4(l[0], l[1], l[2], l[3]);
}

// ---------------- HMMA GEMM: C = A @ B^T via 3-term bf16 split --------------
// A: (4096, 2048) hi/lo; B: (2048, 2048) hi/lo, row n holds K values.
// mode 0: C row-major ldc=D.  mode 1: scatter to (B,H,S,Hd), s = s0 + t.
__global__ __launch_bounds__(256, 2)
void gemm_hmma3(const __nv_bfloat16* __restrict__ Ah, const __nv_bfloat16* __restrict__ Al,
                const __nv_bfloat16* __restrict__ Bh, const __nv_bfloat16* __restrict__ Bl,
                float* __restrict__ C, int mode, int S, int s0)
{
    extern __shared__ char smem[];
    const uint32_t sbase = smem_u32(smem);

    const int tid  = threadIdx.x;
    const int wid  = tid >> 5;
    const int lane = tid & 31;
    const int wm   = wid & 3;    // 4 m-warps x 32 rows
    const int wn   = wid >> 2;   // 2 n-warps x 64 cols

    const int m0 = blockIdx.y * 128;
    const int n0 = blockIdx.x * 128;

    // ---- loader mapping: 2 units (16B) per tile per thread ----
    int r0 = tid >> 2,        g0 = tid & 3;          // unit tid
    int r1 = (tid + 256) >> 2, g1 = tid & 3;         // unit tid+256
    const uint32_t so0 = swoff(r0, g0);
    const uint32_t so1 = swoff(r1, g1);
    const __nv_bfloat16* a0h = Ah + (size_t)(m0 + r0) * D + g0 * 8;
    const __nv_bfloat16* a0l = Al + (size_t)(m0 + r0) * D + g0 * 8;
    const __nv_bfloat16* b0h = Bh + (size_t)(n0 + r0) * D + g0 * 8;
    const __nv_bfloat16* b0l = Bl + (size_t)(n0 + r0) * D + g0 * 8;
    const __nv_bfloat16* a1h = Ah + (size_t)(m0 + r1) * D + g1 * 8;
    const __nv_bfloat16* a1l = Al + (size_t)(m0 + r1) * D + g1 * 8;
    const __nv_bfloat16* b1h = Bh + (size_t)(n0 + r1) * D + g1 * 8;
    const __nv_bfloat16* b1l = Bl + (size_t)(n0 + r1) * D + g1 * 8;

    // ---- ldmatrix lane offsets (within a tile) ----
    uint32_t aoff[2][2], boff[4][2];
    #pragma unroll
    for (int mt = 0; mt < 2; ++mt) {
        int row = wm * 32 + mt * 16 + (lane & 15);
        #pragma unroll
        for (int ks = 0; ks < 2; ++ks)
            aoff[mt][ks] = swoff(row, ks * 2 + (lane >> 4));
    }
    #pragma unroll
    for (int np = 0; np < 4; ++np) {
        int nr = wn * 64 + np * 16 + (lane & 7) + ((lane >> 4) << 3);
        #pragma unroll
        for (int ks = 0; ks < 2; ++ks)
            boff[np][ks] = swoff(nr, ks * 2 + ((lane >> 3) & 1));
    }

    float acc[2][8][4];
    #pragma unroll
    for (int mt = 0; mt < 2; ++mt)
        #pragma unroll
        for (int nt = 0; nt < 8; ++nt)
            #pragma unroll
            for (int v = 0; v < 4; ++v) acc[mt][nt][v] = 0.f;

    const int nchunk = D / 32;   // 64

    // prologue: stages 0, 1
    #pragma unroll
    for (int s = 0; s < NSTAGE - 1; ++s) {
        uint32_t sb = sbase + s * STAGE_B;
        int ko = s * 32;
        cp16(sb + 0*TILE_B + so0, a0h + ko); cp16(sb + 0*TILE_B + so1, a1h + ko);
        cp16(sb + 1*TILE_B + so0, a0l + ko); cp16(sb + 1*TILE_B + so1, a1l + ko);
        cp16(sb + 2*TILE_B + so0, b0h + ko); cp16(sb + 2*TILE_B + so1, b1h + ko);
        cp16(sb + 3*TILE_B + so0, b0l + ko); cp16(sb + 3*TILE_B + so1, b1l + ko);
        CP_COMMIT();
    }

    for (int kc = 0; kc < nchunk; ++kc) {
        if (kc + NSTAGE - 1 < nchunk) {
            uint32_t sb = sbase + ((kc + NSTAGE - 1) % NSTAGE) * STAGE_B;
            int ko = (kc + NSTAGE - 1) * 32;
            cp16(sb + 0*TILE_B + so0, a0h + ko); cp16(sb + 0*TILE_B + so1, a1h + ko);
            cp16(sb + 1*TILE_B + so0, a0l + ko); cp16(sb + 1*TILE_B + so1, a1l + ko);
            cp16(sb + 2*TILE_B + so0, b0h + ko); cp16(sb + 2*TILE_B + so1, b1h + ko);
            cp16(sb + 3*TILE_B + so0, b0l + ko); cp16(sb + 3*TILE_B + so1, b1l + ko);
            CP_COMMIT();
            asm volatile("cp.async.wait_group 2;" ::: "memory");
        } else if (kc + NSTAGE - 2 < nchunk) {
            asm volatile("cp.async.wait_group 1;" ::: "memory");
        } else {
            asm volatile("cp.async.wait_group 0;" ::: "memory");
        }
        __syncthreads();

        const uint32_t sb = sbase + (kc % NSTAGE) * STAGE_B;
        #pragma unroll
        for (int ks = 0; ks < 2; ++ks) {
            uint32_t ah[2][4], al[2][4];
            ldm_x4(ah[0], sb + 0*TILE_B + aoff[0][ks]);
            ldm_x4(ah[1], sb + 0*TILE_B + aoff[1][ks]);
            ldm_x4(al[0], sb + 1*TILE_B + aoff[0][ks]);
            ldm_x4(al[1], sb + 1*TILE_B + aoff[1][ks]);
            #pragma unroll
            for (int np = 0; np < 4; ++np) {
                uint32_t bq[4];
                ldm_x4(bq, sb + 2*TILE_B + boff[np][ks]);   // Bh pair
                #pragma unroll
                for (int mt = 0; mt < 2; ++mt) {
                    mma_bf16(acc[mt][np*2+0], ah[mt], bq + 0);
                    mma_bf16(acc[mt][np*2+1], ah[mt], bq + 2);
                    mma_bf16(acc[mt][np*2+0], al[mt], bq + 0);
                    mma_bf16(acc[mt][np*2+1], al[mt], bq + 2);
                }
                ldm_x4(bq, sb + 3*TILE_B + boff[np][ks]);   // Bl pair
                #pragma unroll
                for (int mt = 0; mt < 2; ++mt) {
                    mma_bf16(acc[mt][np*2+0], ah[mt], bq + 0);
                    mma_bf16(acc[mt][np*2+1], ah[mt], bq + 2);
                }
            }
        }
        __syncthreads();
    }

    // ---- epilogue ----
    const int er = lane >> 2;          // 0..7
    const int ec = (lane & 3) * 2;     // 0,2,4,6
    #pragma unroll
    for (int mt = 0; mt < 2; ++mt) {
        #pragma unroll
        for (int nt = 0; nt < 8; ++nt) {
            int gm = m0 + wm * 32 + mt * 16 + er;
            int gc = n0 + wn * 64 + nt * 8 + ec;
            if (mode == 0) {
                float* dst = C + (size_t)gm * D + gc;
                *(float2*)dst = make_float2(acc[mt][nt][0], acc[mt][nt][1]);
                *(float2*)(dst + 8 * D) = make_float2(acc[mt][nt][2], acc[mt][nt][3]);
            } else {
                int h = gc >> 6, d = gc & 63;
                int b = gm >> 8, t = gm & 255;
                float* dst = C + ((size_t)((b * NH + h) * S + s0 + t)) * HD + d;
                *(float2*)dst = make_float2(acc[mt][nt][0], acc[mt][nt][1]);
                // row gm+8 -> t+8 (same b since 16-row tile never crosses 256)
                float* dst2 = C + ((size_t)((b * NH + h) * S + s0 + t + 8)) * HD + d;
                *(float2*)dst2 = make_float2(acc[mt][nt][2], acc[mt][nt][3]);
            }
        }
    }
}

// ---------------- prep: cache tail copies + RoPE ----------------------------
__global__ void prep_kernel(const float* __restrict__ past_k,
                            const float* __restrict__ past_v,
                            float* __restrict__ new_k,
                            float* __restrict__ new_v,
                            float* __restrict__ q,
                            float* __restrict__ katt,
                            const int* __restrict__ pos_ptr)
{
    int idx = blockIdx.x * blockDim.x + threadIdx.x;
    int j  = idx & 31;
    int s  = (idx >> 5) & 511;
    int bh = idx >> 14;

    if (s < 256) {
        size_t src = ((size_t)bh * SK + (s + 256)) * HD + j * 2;
        size_t dst = ((size_t)bh * SK + s) * HD + j * 2;
        float2 kp = *(const float2*)(past_k + src);
        float2 vp = *(const float2*)(past_v + src);
        *(float2*)(new_k + dst) = kp;
        *(float2*)(katt + dst)  = kp;
        *(float2*)(new_v + dst) = vp;
    } else {
        int t = s - 256;
        float pos = (float)(pos_ptr[0] + t);
        float inv = exp2f(-(float)j * 0.41524101186091403f);
        float ang = pos * inv;
        float sn, cs;
        sincosf(ang, &sn, &cs);

        size_t dk = ((size_t)bh * SK + s) * HD + j * 2;
        float2 kv = *(const float2*)(new_k + dk);
        float2 kr = {kv.x * cs - kv.y * sn, kv.x * sn + kv.y * cs};
        *(float2*)(katt + dk) = kr;

        size_t dq = ((size_t)bh * TT + t) * HD + j * 2;
        float2 qv = *(const float2*)(q + dq);
        float2 qr = {qv.x * cs - qv.y * sn, qv.x * sn + qv.y * cs};
        *(float2*)(q + dq) = qr;
    }
}

// ---------------- attention: flash-style, 64 queries x 32-key chunks --------
__global__ __launch_bounds__(128)
void attn_kernel(const float* __restrict__ Q,
                 const float* __restrict__ K,
                 const float* __restrict__ V,
                 float* __restrict__ O)
{
    __shared__ float Qs[64 * 64];
    __shared__ float Ks[32 * 64];
    __shared__ float Vs[32 * 64];
    __shared__ float Ps[64 * 33];

    const int bh = blockIdx.y;
    const int q0 = blockIdx.x * 64;
    const int tid = threadIdx.x;
    const int tr = tid >> 3;
    const int tc = tid & 7;

    const float scale = 0.125f;

    const float* Qg = Q + ((size_t)bh * TT + q0) * HD;
    for (int i = tid; i < 64 * 16; i += 128) {
        int r = i >> 4, c4 = i & 15;
        float4 v = *(const float4*)(Qg + r * 64 + c4 * 4);
        v.x *= scale; v.y *= scale; v.z *= scale; v.w *= scale;
        int p = c4 ^ ((r >> 2) & 7);
        *(float4*)&Qs[r * 64 + p * 4] = v;
    }

    float mrow[4], lrow[4], acc[4][8];
    #pragma unroll
    for (int i = 0; i < 4; ++i) {
        mrow[i] = -1e30f; lrow[i] = 0.f;
        #pragma unroll
        for (int j = 0; j < 8; ++j) acc[i][j] = 0.f;
    }

    const int nchunk = min(16, ((q0 + 319) >> 5) + 1);
    const float* Kg = K + (size_t)bh * SK * HD;
    const float* Vg = V + (size_t)bh * SK * HD;

    for (int c = 0; c < nchunk; ++c) {
        __syncthreads();
        for (int i = tid; i < 512; i += 128) {
            int r = i >> 4, c4 = i & 15;
            int p = c4 ^ ((r >> 2) & 7);
            const float* kp = Kg + (c * 32 + r) * 64 + c4 * 4;
            const float* vp = Vg + (c * 32 + r) * 64 + c4 * 4;
            *(float4*)&Ks[r * 64 + p * 4] = *(const float4*)kp;
            *(float4*)&Vs[r * 64 + p * 4] = *(const float4*)vp;
        }
        __syncthreads();

        float Sv[4][4];
        #pragma unroll
        for (int i = 0; i < 4; ++i)
            #pragma unroll
            for (int j = 0; j < 4; ++j) Sv[i][j] = 0.f;

        #pragma unroll
        for (int d4 = 0; d4 < 16; ++d4) {
            float4 a[4];
            int pq = (d4 ^ (tr & 7)) * 4;
            #pragma unroll
            for (int i = 0; i < 4; ++i)
                a[i] = *(const float4*)&Qs[(tr * 4 + i) * 64 + pq];
            int pk = (d4 ^ tc) * 4;
            #pragma unroll
            for (int j = 0; j < 4; ++j) {
                float4 b = *(const float4*)&Ks[(tc * 4 + j) * 64 + pk];
                #pragma unroll
                for (int i = 0; i < 4; ++i)
                    Sv[i][j] += a[i].x * b.x + a[i].y * b.y + a[i].z * b.z + a[i].w * b.w;
            }
        }

        #pragma unroll
        for (int i = 0; i < 4; ++i) {
            int t = q0 + tr * 4 + i;
            #pragma unroll
            for (int j = 0; j < 4; ++j) {
                int s = c * 32 + tc * 4 + j;
                if (s > t + 256) Sv[i][j] = -1e30f;
            }
        }

        float mn[4];
        #pragma unroll
        for (int i = 0; i < 4; ++i)
            mn[i] = fmaxf(fmaxf(Sv[i][0], Sv[i][1]), fmaxf(Sv[i][2], Sv[i][3]));
        #pragma unroll
        for (int o = 1; o < 8; o <<= 1)
            #pragma unroll
            for (int i = 0; i < 4; ++i)
                mn[i] = fmaxf(mn[i], __shfl_xor_sync(0xffffffffu, mn[i], o));

        float rs[4];
        #pragma unroll
        for (int i = 0; i < 4; ++i) {
            float mN = fmaxf(mrow[i], mn[i]);
            float sc = __expf(mrow[i] - mN);
            mrow[i] = mN;
            float r = 0.f;
            #pragma unroll
            for (int j = 0; j < 4; ++j) {
                float p = __expf(Sv[i][j] - mN);
                Sv[i][j] = p;
                r += p;
            }
            rs[i] = r;
            lrow[i] *= sc;
            #pragma unroll
            for (int j = 0; j < 8; ++j) acc[i][j] *= sc;
        }
        #pragma unroll
        for (int o = 1; o < 8; o <<= 1)
            #pragma unroll
            for (int i = 0; i < 4; ++i)
                rs[i] += __shfl_xor_sync(0xffffffffu, rs[i], o);
        #pragma unroll
        for (int i = 0; i < 4; ++i) lrow[i] += rs[i];

        #pragma unroll
        for (int i = 0; i < 4; ++i)
            #pragma unroll
            for (int j = 0; j < 4; ++j)
                Ps[(tr * 4 + i) * 33 + tc * 4 + j] = Sv[i][j];
        __syncthreads();

        #pragma unroll 4
        for (int k = 0; k < 32; ++k) {
            int sw_ = (k >> 2) & 7;
            float4 v0 = *(const float4*)&Vs[k * 64 + ((tc * 2)     ^ sw_) * 4];
            float4 v1 = *(const float4*)&Vs[k * 64 + ((tc * 2 + 1) ^ sw_) * 4];
            float pp[4];
            #pragma unroll
            for (int i = 0; i < 4; ++i) pp[i] = Ps[(tr * 4 + i) * 33 + k];
            #pragma unroll
            for (int i = 0; i < 4; ++i) {
                acc[i][0] += pp[i] * v0.x; acc[i][1] += pp[i] * v0.y;
                acc[i][2] += pp[i] * v0.z; acc[i][3] += pp[i] * v0.w;
                acc[i][4] += pp[i] * v1.x; acc[i][5] += pp[i] * v1.y;
                acc[i][6] += pp[i] * v1.z; acc[i][7] += pp[i] * v1.w;
            }
        }
    }

    const int b = bh >> 5;
    const int h = bh & 31;
    #pragma unroll
    for (int i = 0; i < 4; ++i) {
        float inv = 1.0f / lrow[i];
        int t = q0 + tr * 4 + i;
        float* dst = O + ((size_t)(b * TT + t)) * D + h * HD + tc * 8;
        float4 o0 = {acc[i][0] * inv, acc[i][1] * inv, acc[i][2] * inv, acc[i][3] * inv};
        float4 o1 = {acc[i][4] * inv, acc[i][5] * inv, acc[i][6] * inv, acc[i][7] * inv};
        *(float4*)(dst)     = o0;
        *(float4*)(dst + 4) = o1;
    }
}

// ---------------- launch ----------------------------------------------------
extern "C" void kernel_launch(void* const* d_in, const int* in_sizes, int n_in,
                              void* d_out, int out_size)
{
    const float* x      = (const float*)d_in[0];
    const float* past_k = (const float*)d_in[1];
    const float* past_v = (const float*)d_in[2];
    const float* Wq     = (const float*)d_in[3];
    const float* Wk     = (const float*)d_in[4];
    const float* Wv     = (const float*)d_in[5];
    const float* Wo     = (const float*)d_in[6];
    const int*   pos    = (const int*)d_in[7];

    float* out   = (float*)d_out;
    float* new_k = out + OFF_K;
    float* new_v = out + OFF_V;

    float *q_ptr, *katt_ptr, *oattn_ptr;
    __nv_bfloat16 *xh, *xl, *oh, *ol, *wh, *wl;
    cudaGetSymbolAddress((void**)&q_ptr,     g_q);
    cudaGetSymbolAddress((void**)&katt_ptr,  g_katt);
    cudaGetSymbolAddress((void**)&oattn_ptr, g_oattn);
    cudaGetSymbolAddress((void**)&xh, g_xh);
    cudaGetSymbolAddress((void**)&xl, g_xl);
    cudaGetSymbolAddress((void**)&oh, g_oh);
    cudaGetSymbolAddress((void**)&ol, g_ol);
    cudaGetSymbolAddress((void**)&wh, g_wh);
    cudaGetSymbolAddress((void**)&wl, g_wl);

    cudaFuncSetAttribute(gemm_hmma3, cudaFuncAttributeMaxDynamicSharedMemorySize, GEMM_SMEM);

    const int NX4 = BT * D / 4;
    const int NW4 = D * D / 4;

    split_kernel<<<NX4 / 256, 256>>>((const float4*)x, (ushort4*)xh, (ushort4*)xl, NX4);
    split_kernel<<<NW4 / 256, 256>>>((const float4*)Wq, (ushort4*)(wh + 0 * (size_t)D * D), (ushort4*)(wl + 0 * (size_t)D * D), NW4);
    split_kernel<<<NW4 / 256, 256>>>((const float4*)Wk, (ushort4*)(wh + 1 * (size_t)D * D), (ushort4*)(wl + 1 * (size_t)D * D), NW4);
    split_kernel<<<NW4 / 256, 256>>>((const float4*)Wv, (ushort4*)(wh + 2 * (size_t)D * D), (ushort4*)(wl + 2 * (size_t)D * D), NW4);
    split_kernel<<<NW4 / 256, 256>>>((const float4*)Wo, (ushort4*)(wh + 3 * (size_t)D * D), (ushort4*)(wl + 3 * (size_t)D * D), NW4);

    dim3 ggrid(D / 128, BT / 128);   // (16, 32)

    gemm_hmma3<<<ggrid, 256, GEMM_SMEM>>>(xh, xl, wh + 0 * (size_t)D * D, wl + 0 * (size_t)D * D, q_ptr, 1, TT, 0);
    gemm_hmma3<<<ggrid, 256, GEMM_SMEM>>>(xh, xl, wh + 1 * (size_t)D * D, wl + 1 * (size_t)D * D, new_k, 1, SK, 256);
    gemm_hmma3<<<ggrid, 256, GEMM_SMEM>>>(xh, xl, wh + 2 * (size_t)D * D, wl + 2 * (size_t)D * D, new_v, 1, SK, 256);

    prep_kernel<<<(NB * NH * SK * 32) / 256, 256>>>(past_k, past_v, new_k, new_v,
                                                    q_ptr, katt_ptr, pos);

    attn_kernel<<<dim3(TT / 64, NB * NH), 128>>>(q_ptr, katt_ptr, new_v, oattn_ptr);

    split_kernel<<<NX4 / 256, 256>>>((const float4*)oattn_ptr, (ushort4*)oh, (ushort4*)ol, NX4);
    gemm_hmma3<<<ggrid, 256, GEMM_SMEM>>>(oh, ol, wh + 3 * (size_t)D * D, wl + 3 * (size_t)D * D, out, 0, 0, 0);

    (void)in_sizes; (void)n_in; (void)out_size;
}

// round 11
// speedup vs baseline: 2.8851x; 1.2968x over previous
#include <cuda_runtime.h>
#include <cuda_bf16.h>
#include <cstdint>
#include <math.h>

#define D    2048
#define NH   32
#define HD   64
#define TT   256
#define NB   16
#define SK   512
#define BT   (NB*TT)   // 4096

#define OFF_K (BT*D)
#define NKV   (NB*NH*SK*HD)
#define OFF_V (OFF_K + NKV)

// ---------------- scratch (device globals; no allocation allowed) ----------
__device__ float g_q[NB*NH*TT*HD];     // Q proj (B,H,T,Hd) fp32 (pre-rope)

__device__ __nv_bfloat16 g_xh[BT*D], g_xl[BT*D];     // split x
__device__ __nv_bfloat16 g_oh[BT*D], g_ol[BT*D];     // split attention out
__device__ __nv_bfloat16 g_wh[4][D*D], g_wl[4][D*D]; // split Wq,Wk,Wv,Wo

__device__ __nv_bfloat16 g_qh[NB*NH*TT*HD], g_ql[NB*NH*TT*HD]; // rope'd+scaled Q
__device__ __nv_bfloat16 g_kh[NKV], g_kl[NKV];       // attention K split
__device__ __nv_bfloat16 g_vh[NKV], g_vl[NKV];       // V split

// ---------------- helpers ---------------------------------------------------
__device__ __forceinline__ uint32_t smem_u32(const void* p) {
    uint32_t a;
    asm("{ .reg .u64 t; cvta.to.shared.u64 t, %1; cvt.u32.u64 %0, t; }" : "=r"(a) : "l"(p));
    return a;
}
__device__ __forceinline__ void cp16(uint32_t dst, const void* src) {
    asm volatile("cp.async.cg.shared.global [%0], [%1], 16;" :: "r"(dst), "l"(src));
}
#define CP_COMMIT() asm volatile("cp.async.commit_group;" ::: "memory")

__device__ __forceinline__ void ldm_x4(uint32_t* r, uint32_t addr) {
    asm volatile("ldmatrix.sync.aligned.m8n8.x4.shared.b16 {%0,%1,%2,%3}, [%4];"
        : "=r"(r[0]), "=r"(r[1]), "=r"(r[2]), "=r"(r[3]) : "r"(addr));
}
__device__ __forceinline__ void ldm_x4t(uint32_t* r, uint32_t addr) {
    asm volatile("ldmatrix.sync.aligned.m8n8.x4.trans.shared.b16 {%0,%1,%2,%3}, [%4];"
        : "=r"(r[0]), "=r"(r[1]), "=r"(r[2]), "=r"(r[3]) : "r"(addr));
}
__device__ __forceinline__ void mma_bf16(float* c, const uint32_t* a, const uint32_t* b) {
    asm volatile(
        "mma.sync.aligned.m16n8k16.row.col.f32.bf16.bf16.f32 "
        "{%0,%1,%2,%3}, {%4,%5,%6,%7}, {%8,%9}, {%0,%1,%2,%3};"
        : "+f"(c[0]), "+f"(c[1]), "+f"(c[2]), "+f"(c[3])
        : "r"(a[0]), "r"(a[1]), "r"(a[2]), "r"(a[3]), "r"(b[0]), "r"(b[1]));
}
// pack two floats to bf16x2: 'lo' -> low half, 'hi' -> high half
__device__ __forceinline__ uint32_t pk(float lo, float hi) {
    uint32_t r;
    asm("cvt.rn.bf16x2.f32 %0, %1, %2;" : "=r"(r) : "f"(hi), "f"(lo));
    return r;
}
__device__ __forceinline__ float bhi(float x) {
    __nv_bfloat16 h = __float2bfloat16(x);
    return __bfloat162float(h);
}

// gemm smem tile: rows x 32 bf16 (64B rows), xor swizzle
__device__ __forceinline__ uint32_t swoff(int r, int g) {
    return (uint32_t)(r * 64 + ((g ^ ((r >> 1) & 3)) * 16));
}
// attention smem tile: rows x 64 bf16 (128B rows), xor swizzle
__device__ __forceinline__ uint32_t vsw(int r, int g) {
    return (uint32_t)(r * 128 + ((g ^ (r & 7)) * 16));
}

#define TILE_B   8192                 // 128 x 64B
#define STAGE_B  (4 * TILE_B)         // Ah | Al | Bh | Bl
#define NSTAGE   3
#define GEMM_SMEM (NSTAGE * STAGE_B)  // 98304

#define ATT_STAGE 32768               // Kh | Kl | Vh | Vl (8KB each)
#define ATT_SMEM  (16384 + 3 * ATT_STAGE)   // Qh,Ql + 3 KV stages = 114688

// ---------------- split: fp32 -> bf16 hi + bf16 lo --------------------------
__global__ void split_kernel(const float4* __restrict__ src,
                             ushort4* __restrict__ hi, ushort4* __restrict__ lo, int n4)
{
    int i = blockIdx.x * blockDim.x + threadIdx.x;
    if (i >= n4) return;
    float4 v = src[i];
    float f[4] = {v.x, v.y, v.z, v.w};
    unsigned short h[4], l[4];
    #pragma unroll
    for (int j = 0; j < 4; ++j) {
        __nv_bfloat16 hb = __float2bfloat16(f[j]);
        float hf = __bfloat162float(hb);
        __nv_bfloat16 lb = __float2bfloat16(f[j] - hf);
        h[j] = *reinterpret_cast<unsigned short*>(&hb);
        l[j] = *reinterpret_cast<unsigned short*>(&lb);
    }
    hi[i] = make_ushort4(h[0], h[1], h[2], h[3]);
    lo[i] = make_ushort4(l[0], l[1], l[2], l[3]);
}

// ---------------- HMMA GEMM: C = A @ B^T via 3-term bf16 split --------------
__global__ __launch_bounds__(256, 2)
void gemm_hmma3(const __nv_bfloat16* __restrict__ Ah, const __nv_bfloat16* __restrict__ Al,
                const __nv_bfloat16* __restrict__ Bh, const __nv_bfloat16* __restrict__ Bl,
                float* __restrict__ C, int mode, int S, int s0)
{
    extern __shared__ char smem[];
    const uint32_t sbase = smem_u32(smem);

    const int tid  = threadIdx.x;
    const int wid  = tid >> 5;
    const int lane = tid & 31;
    const int wm   = wid & 3;
    const int wn   = wid >> 2;

    const int m0 = blockIdx.y * 128;
    const int n0 = blockIdx.x * 128;

    int r0 = tid >> 2,         g0 = tid & 3;
    int r1 = (tid + 256) >> 2, g1 = tid & 3;
    const uint32_t so0 = swoff(r0, g0);
    const uint32_t so1 = swoff(r1, g1);
    const __nv_bfloat16* a0h = Ah + (size_t)(m0 + r0) * D + g0 * 8;
    const __nv_bfloat16* a0l = Al + (size_t)(m0 + r0) * D + g0 * 8;
    const __nv_bfloat16* b0h = Bh + (size_t)(n0 + r0) * D + g0 * 8;
    const __nv_bfloat16* b0l = Bl + (size_t)(n0 + r0) * D + g0 * 8;
    const __nv_bfloat16* a1h = Ah + (size_t)(m0 + r1) * D + g1 * 8;
    const __nv_bfloat16* a1l = Al + (size_t)(m0 + r1) * D + g1 * 8;
    const __nv_bfloat16* b1h = Bh + (size_t)(n0 + r1) * D + g1 * 8;
    const __nv_bfloat16* b1l = Bl + (size_t)(n0 + r1) * D + g1 * 8;

    uint32_t aoff[2][2], boff[4][2];
    #pragma unroll
    for (int mt = 0; mt < 2; ++mt) {
        int row = wm * 32 + mt * 16 + (lane & 15);
        #pragma unroll
        for (int ks = 0; ks < 2; ++ks)
            aoff[mt][ks] = swoff(row, ks * 2 + (lane >> 4));
    }
    #pragma unroll
    for (int np = 0; np < 4; ++np) {
        int nr = wn * 64 + np * 16 + (lane & 7) + ((lane >> 4) << 3);
        #pragma unroll
        for (int ks = 0; ks < 2; ++ks)
            boff[np][ks] = swoff(nr, ks * 2 + ((lane >> 3) & 1));
    }

    float acc[2][8][4];
    #pragma unroll
    for (int mt = 0; mt < 2; ++mt)
        #pragma unroll
        for (int nt = 0; nt < 8; ++nt)
            #pragma unroll
            for (int v = 0; v < 4; ++v) acc[mt][nt][v] = 0.f;

    const int nchunk = D / 32;   // 64

    #pragma unroll
    for (int s = 0; s < NSTAGE - 1; ++s) {
        uint32_t sb = sbase + s * STAGE_B;
        int ko = s * 32;
        cp16(sb + 0*TILE_B + so0, a0h + ko); cp16(sb + 0*TILE_B + so1, a1h + ko);
        cp16(sb + 1*TILE_B + so0, a0l + ko); cp16(sb + 1*TILE_B + so1, a1l + ko);
        cp16(sb + 2*TILE_B + so0, b0h + ko); cp16(sb + 2*TILE_B + so1, b1h + ko);
        cp16(sb + 3*TILE_B + so0, b0l + ko); cp16(sb + 3*TILE_B + so1, b1l + ko);
        CP_COMMIT();
    }

    for (int kc = 0; kc < nchunk; ++kc) {
        if (kc + 1 < nchunk) asm volatile("cp.async.wait_group 1;" ::: "memory");
        else                 asm volatile("cp.async.wait_group 0;" ::: "memory");
        __syncthreads();

        if (kc + NSTAGE - 1 < nchunk) {
            uint32_t sb = sbase + ((kc + NSTAGE - 1) % NSTAGE) * STAGE_B;
            int ko = (kc + NSTAGE - 1) * 32;
            cp16(sb + 0*TILE_B + so0, a0h + ko); cp16(sb + 0*TILE_B + so1, a1h + ko);
            cp16(sb + 1*TILE_B + so0, a0l + ko); cp16(sb + 1*TILE_B + so1, a1l + ko);
            cp16(sb + 2*TILE_B + so0, b0h + ko); cp16(sb + 2*TILE_B + so1, b1h + ko);
            cp16(sb + 3*TILE_B + so0, b0l + ko); cp16(sb + 3*TILE_B + so1, b1l + ko);
            CP_COMMIT();
        }

        const uint32_t sb = sbase + (kc % NSTAGE) * STAGE_B;
        #pragma unroll
        for (int ks = 0; ks < 2; ++ks) {
            uint32_t ah[2][4], al[2][4];
            ldm_x4(ah[0], sb + 0*TILE_B + aoff[0][ks]);
            ldm_x4(ah[1], sb + 0*TILE_B + aoff[1][ks]);
            ldm_x4(al[0], sb + 1*TILE_B + aoff[0][ks]);
            ldm_x4(al[1], sb + 1*TILE_B + aoff[1][ks]);
            #pragma unroll
            for (int np = 0; np < 4; ++np) {
                uint32_t bq[4];
                ldm_x4(bq, sb + 2*TILE_B + boff[np][ks]);
                #pragma unroll
                for (int mt = 0; mt < 2; ++mt) {
                    mma_bf16(acc[mt][np*2+0], ah[mt], bq + 0);
                    mma_bf16(acc[mt][np*2+1], ah[mt], bq + 2);
                    mma_bf16(acc[mt][np*2+0], al[mt], bq + 0);
                    mma_bf16(acc[mt][np*2+1], al[mt], bq + 2);
                }
                ldm_x4(bq, sb + 3*TILE_B + boff[np][ks]);
                #pragma unroll
                for (int mt = 0; mt < 2; ++mt) {
                    mma_bf16(acc[mt][np*2+0], ah[mt], bq + 0);
                    mma_bf16(acc[mt][np*2+1], ah[mt], bq + 2);
                }
            }
        }
    }

    const int er = lane >> 2;
    const int ec = (lane & 3) * 2;
    #pragma unroll
    for (int mt = 0; mt < 2; ++mt) {
        #pragma unroll
        for (int nt = 0; nt < 8; ++nt) {
            int gm = m0 + wm * 32 + mt * 16 + er;
            int gc = n0 + wn * 64 + nt * 8 + ec;
            if (mode == 0) {
                float* dst = C + (size_t)gm * D + gc;
                *(float2*)dst = make_float2(acc[mt][nt][0], acc[mt][nt][1]);
                *(float2*)(dst + 8 * D) = make_float2(acc[mt][nt][2], acc[mt][nt][3]);
            } else {
                int h = gc >> 6, d = gc & 63;
                int b = gm >> 8, t = gm & 255;
                float* dst = C + ((size_t)((b * NH + h) * S + s0 + t)) * HD + d;
                *(float2*)dst = make_float2(acc[mt][nt][0], acc[mt][nt][1]);
                float* dst2 = C + ((size_t)((b * NH + h) * S + s0 + t + 8)) * HD + d;
                *(float2*)dst2 = make_float2(acc[mt][nt][2], acc[mt][nt][3]);
            }
        }
    }
}

// ---------------- prep: cache tail copies + RoPE + bf16 splits --------------
__global__ void prep_kernel(const float* __restrict__ past_k,
                            const float* __restrict__ past_v,
                            float* __restrict__ new_k,
                            float* __restrict__ new_v,
                            const float* __restrict__ q,
                            const int* __restrict__ pos_ptr,
                            __nv_bfloat16* __restrict__ qh, __nv_bfloat16* __restrict__ ql,
                            __nv_bfloat16* __restrict__ kh, __nv_bfloat16* __restrict__ kl,
                            __nv_bfloat16* __restrict__ vh, __nv_bfloat16* __restrict__ vl)
{
    int idx = blockIdx.x * blockDim.x + threadIdx.x;
    int j  = idx & 31;
    int s  = (idx >> 5) & 511;
    int bh = idx >> 14;

    size_t dk = ((size_t)bh * SK + s) * HD + j * 2;

    if (s < 256) {
        size_t src = ((size_t)bh * SK + (s + 256)) * HD + j * 2;
        float2 kp = *(const float2*)(past_k + src);
        float2 vp = *(const float2*)(past_v + src);
        *(float2*)(new_k + dk) = kp;
        *(float2*)(new_v + dk) = vp;
        float kh0 = bhi(kp.x), kh1 = bhi(kp.y);
        *(uint32_t*)(kh + dk) = pk(kh0, kh1);
        *(uint32_t*)(kl + dk) = pk(kp.x - kh0, kp.y - kh1);
        float vh0 = bhi(vp.x), vh1 = bhi(vp.y);
        *(uint32_t*)(vh + dk) = pk(vh0, vh1);
        *(uint32_t*)(vl + dk) = pk(vp.x - vh0, vp.y - vh1);
    } else {
        int t = s - 256;
        float pos = (float)(pos_ptr[0] + t);
        float inv = exp2f(-(float)j * 0.41524101186091403f);
        float ang = pos * inv;
        float sn, cs;
        sincosf(ang, &sn, &cs);

        float2 kv = *(const float2*)(new_k + dk);
        float2 kr = {kv.x * cs - kv.y * sn, kv.x * sn + kv.y * cs};
        float kh0 = bhi(kr.x), kh1 = bhi(kr.y);
        *(uint32_t*)(kh + dk) = pk(kh0, kh1);
        *(uint32_t*)(kl + dk) = pk(kr.x - kh0, kr.y - kh1);

        float2 vp = *(const float2*)(new_v + dk);
        float vh0 = bhi(vp.x), vh1 = bhi(vp.y);
        *(uint32_t*)(vh + dk) = pk(vh0, vh1);
        *(uint32_t*)(vl + dk) = pk(vp.x - vh0, vp.y - vh1);

        size_t dq = ((size_t)bh * TT + t) * HD + j * 2;
        float2 qv = *(const float2*)(q + dq);
        float2 qr = {(qv.x * cs - qv.y * sn) * 0.125f, (qv.x * sn + qv.y * cs) * 0.125f};
        float qh0 = bhi(qr.x), qh1 = bhi(qr.y);
        *(uint32_t*)(qh + dq) = pk(qh0, qh1);
        *(uint32_t*)(ql + dq) = pk(qr.x - qh0, qr.y - qh1);
    }
}

// ---------------- attention: HMMA flash, 64 q x 64-key chunks ---------------
__global__ __launch_bounds__(128)
void attn_hmma(const __nv_bfloat16* __restrict__ Qh, const __nv_bfloat16* __restrict__ Ql,
               const __nv_bfloat16* __restrict__ Kh, const __nv_bfloat16* __restrict__ Kl,
               const __nv_bfloat16* __restrict__ Vh, const __nv_bfloat16* __restrict__ Vl,
               __nv_bfloat16* __restrict__ Oh, __nv_bfloat16* __restrict__ Ol)
{
    extern __shared__ char sm[];
    const uint32_t sb = smem_u32(sm);
    const int tid = threadIdx.x, wid = tid >> 5, lane = tid & 31;
    const int bh = blockIdx.y, q0 = blockIdx.x * 64;

    const __nv_bfloat16* Qhg = Qh + ((size_t)bh * TT + q0) * HD;
    const __nv_bfloat16* Qlg = Ql + ((size_t)bh * TT + q0) * HD;
    const __nv_bfloat16* Khg = Kh + (size_t)bh * SK * HD;
    const __nv_bfloat16* Klg = Kl + (size_t)bh * SK * HD;
    const __nv_bfloat16* Vhg = Vh + (size_t)bh * SK * HD;
    const __nv_bfloat16* Vlg = Vl + (size_t)bh * SK * HD;

    // Q tiles (group 0)
    #pragma unroll
    for (int i = 0; i < 4; ++i) {
        int u = i * 128 + tid, r = u >> 3, g = u & 7;
        uint32_t off = vsw(r, g);
        cp16(sb + off,        Qhg + r * HD + g * 8);
        cp16(sb + 8192 + off, Qlg + r * HD + g * 8);
    }
    CP_COMMIT();

    const int nchunk = (q0 + 320) >> 6;   // 5..8

    // chunk 0 (group 1)
    {
        uint32_t st = sb + 16384;
        #pragma unroll
        for (int i = 0; i < 4; ++i) {
            int u = i * 128 + tid, r = u >> 3, g = u & 7;
            uint32_t off = vsw(r, g);
            int go = r * HD + g * 8;
            cp16(st + off,         Khg + go);
            cp16(st + 8192 + off,  Klg + go);
            cp16(st + 16384 + off, Vhg + go);
            cp16(st + 24576 + off, Vlg + go);
        }
        CP_COMMIT();
    }

    float m0r = -1e30f, m1r = -1e30f, l0 = 0.f, l1 = 0.f;
    float oacc[8][4];
    #pragma unroll
    for (int f = 0; f < 8; ++f)
        #pragma unroll
        for (int v = 0; v < 4; ++v) oacc[f][v] = 0.f;

    const int arow  = (wid << 4) + (lane & 15);
    const int acolb = lane >> 4;
    const int brow  = (lane & 7) + ((lane >> 4) << 3);
    const int bcol  = (lane >> 3) & 1;
    const int vrow  = (((lane >> 3) & 1) << 3) + (lane & 7);
    const int vcolb = lane >> 4;
    const int t0    = q0 + (wid << 4) + (lane >> 2);

    for (int c = 0; c < nchunk; ++c) {
        if (c + 1 < nchunk) {
            uint32_t st = sb + 16384 + ((c + 1) % 3) * ATT_STAGE;
            int s0 = (c + 1) * 64;
            #pragma unroll
            for (int i = 0; i < 4; ++i) {
                int u = i * 128 + tid, r = u >> 3, g = u & 7;
                uint32_t off = vsw(r, g);
                int go = (s0 + r) * HD + g * 8;
                cp16(st + off,         Khg + go);
                cp16(st + 8192 + off,  Klg + go);
                cp16(st + 16384 + off, Vhg + go);
                cp16(st + 24576 + off, Vlg + go);
            }
            CP_COMMIT();
            asm volatile("cp.async.wait_group 1;" ::: "memory");
        } else {
            asm volatile("cp.async.wait_group 0;" ::: "memory");
        }
        __syncthreads();

        const uint32_t kb = sb + 16384 + (c % 3) * ATT_STAGE;

        // ---- S = Q K^T (3-term) ----
        float sacc[8][4];
        #pragma unroll
        for (int f = 0; f < 8; ++f)
            #pragma unroll
            for (int v = 0; v < 4; ++v) sacc[f][v] = 0.f;

        #pragma unroll
        for (int ks = 0; ks < 4; ++ks) {
            uint32_t aQh[4], aQl[4];
            ldm_x4(aQh, sb + vsw(arow, ks * 2 + acolb));
            ldm_x4(aQl, sb + 8192 + vsw(arow, ks * 2 + acolb));
            #pragma unroll
            for (int p = 0; p < 4; ++p) {
                uint32_t bk[4];
                ldm_x4(bk, kb + vsw(p * 16 + brow, ks * 2 + bcol));
                mma_bf16(sacc[2*p],   aQh, bk + 0);
                mma_bf16(sacc[2*p+1], aQh, bk + 2);
                mma_bf16(sacc[2*p],   aQl, bk + 0);
                mma_bf16(sacc[2*p+1], aQl, bk + 2);
                ldm_x4(bk, kb + 8192 + vsw(p * 16 + brow, ks * 2 + bcol));
                mma_bf16(sacc[2*p],   aQh, bk + 0);
                mma_bf16(sacc[2*p+1], aQh, bk + 2);
            }
        }

        // ---- mask ----
        if (c * 64 + 63 > q0 + (wid << 4) + 256) {
            #pragma unroll
            for (int f = 0; f < 8; ++f) {
                int s = c * 64 + f * 8 + ((lane & 3) << 1);
                if (s     > t0 + 256) sacc[f][0] = -1e30f;
                if (s + 1 > t0 + 256) sacc[f][1] = -1e30f;
                if (s     > t0 + 264) sacc[f][2] = -1e30f;
                if (s + 1 > t0 + 264) sacc[f][3] = -1e30f;
            }
        }

        // ---- online softmax ----
        float mx0 = -1e30f, mx1 = -1e30f;
        #pragma unroll
        for (int f = 0; f < 8; ++f) {
            mx0 = fmaxf(mx0, fmaxf(sacc[f][0], sacc[f][1]));
            mx1 = fmaxf(mx1, fmaxf(sacc[f][2], sacc[f][3]));
        }
        mx0 = fmaxf(mx0, __shfl_xor_sync(0xffffffffu, mx0, 1));
        mx0 = fmaxf(mx0, __shfl_xor_sync(0xffffffffu, mx0, 2));
        mx1 = fmaxf(mx1, __shfl_xor_sync(0xffffffffu, mx1, 1));
        mx1 = fmaxf(mx1, __shfl_xor_sync(0xffffffffu, mx1, 2));

        float mn0 = fmaxf(m0r, mx0), mn1 = fmaxf(m1r, mx1);
        float e0 = __expf(m0r - mn0), e1 = __expf(m1r - mn1);
        m0r = mn0; m1r = mn1;

        float rs0 = 0.f, rs1 = 0.f;
        #pragma unroll
        for (int f = 0; f < 8; ++f) {
            float p0 = __expf(sacc[f][0] - mn0); sacc[f][0] = p0; rs0 += p0;
            float p1 = __expf(sacc[f][1] - mn0); sacc[f][1] = p1; rs0 += p1;
            float p2 = __expf(sacc[f][2] - mn1); sacc[f][2] = p2; rs1 += p2;
            float p3 = __expf(sacc[f][3] - mn1); sacc[f][3] = p3; rs1 += p3;
        }
        rs0 += __shfl_xor_sync(0xffffffffu, rs0, 1);
        rs0 += __shfl_xor_sync(0xffffffffu, rs0, 2);
        rs1 += __shfl_xor_sync(0xffffffffu, rs1, 1);
        rs1 += __shfl_xor_sync(0xffffffffu, rs1, 2);
        l0 = l0 * e0 + rs0;
        l1 = l1 * e1 + rs1;

        #pragma unroll
        for (int f = 0; f < 8; ++f) {
            oacc[f][0] *= e0; oacc[f][1] *= e0;
            oacc[f][2] *= e1; oacc[f][3] *= e1;
        }

        // ---- O += P V (3-term, P from registers) ----
        #pragma unroll
        for (int ks = 0; ks < 4; ++ks) {
            const int f0 = 2 * ks, f1 = 2 * ks + 1;
            float h00 = bhi(sacc[f0][0]), h01 = bhi(sacc[f0][1]);
            float h02 = bhi(sacc[f0][2]), h03 = bhi(sacc[f0][3]);
            float h10 = bhi(sacc[f1][0]), h11 = bhi(sacc[f1][1]);
            float h12 = bhi(sacc[f1][2]), h13 = bhi(sacc[f1][3]);
            uint32_t pha[4] = { pk(h00, h01), pk(h02, h03), pk(h10, h11), pk(h12, h13) };
            uint32_t pla[4] = { pk(sacc[f0][0]-h00, sacc[f0][1]-h01),
                                pk(sacc[f0][2]-h02, sacc[f0][3]-h03),
                                pk(sacc[f1][0]-h10, sacc[f1][1]-h11),
                                pk(sacc[f1][2]-h12, sacc[f1][3]-h13) };
            #pragma unroll
            for (int p = 0; p < 4; ++p) {
                uint32_t bv[4];
                ldm_x4t(bv, kb + 16384 + vsw(ks * 16 + vrow, p * 2 + vcolb));
                mma_bf16(oacc[2*p],   pha, bv + 0);
                mma_bf16(oacc[2*p+1], pha, bv + 2);
                mma_bf16(oacc[2*p],   pla, bv + 0);
                mma_bf16(oacc[2*p+1], pla, bv + 2);
                ldm_x4t(bv, kb + 24576 + vsw(ks * 16 + vrow, p * 2 + vcolb));
                mma_bf16(oacc[2*p],   pha, bv + 0);
                mma_bf16(oacc[2*p+1], pha, bv + 2);
            }
        }
    }

    // ---- epilogue: write bf16 hi/lo split of O in (B,T,D) ----
    const float inv0 = 1.f / l0, inv1 = 1.f / l1;
    const int b = bh >> 5, h = bh & 31;
    const int d0 = h * 64 + ((lane & 3) << 1);
    #pragma unroll
    for (int f = 0; f < 8; ++f) {
        size_t i0 = ((size_t)(b * TT + t0)) * D + d0 + f * 8;
        size_t i1 = ((size_t)(b * TT + t0 + 8)) * D + d0 + f * 8;
        float v0 = oacc[f][0] * inv0, v1 = oacc[f][1] * inv0;
        float v2 = oacc[f][2] * inv1, v3 = oacc[f][3] * inv1;
        float a0 = bhi(v0), a1 = bhi(v1), a2 = bhi(v2), a3 = bhi(v3);
        *(uint32_t*)(Oh + i0) = pk(a0, a1);
        *(uint32_t*)(Ol + i0) = pk(v0 - a0, v1 - a1);
        *(uint32_t*)(Oh + i1) = pk(a2, a3);
        *(uint32_t*)(Ol + i1) = pk(v2 - a2, v3 - a3);
    }
}

// ---------------- launch ----------------------------------------------------
extern "C" void kernel_launch(void* const* d_in, const int* in_sizes, int n_in,
                              void* d_out, int out_size)
{
    const float* x      = (const float*)d_in[0];
    const float* past_k = (const float*)d_in[1];
    const float* past_v = (const float*)d_in[2];
    const float* Wq     = (const float*)d_in[3];
    const float* Wk     = (const float*)d_in[4];
    const float* Wv     = (const float*)d_in[5];
    const float* Wo     = (const float*)d_in[6];
    const int*   pos    = (const int*)d_in[7];

    float* out   = (float*)d_out;
    float* new_k = out + OFF_K;
    float* new_v = out + OFF_V;

    float* q_ptr;
    __nv_bfloat16 *xh, *xl, *oh, *ol, *wh, *wl, *qh, *ql, *kh, *kl, *vh, *vl;
    cudaGetSymbolAddress((void**)&q_ptr, g_q);
    cudaGetSymbolAddress((void**)&xh, g_xh);
    cudaGetSymbolAddress((void**)&xl, g_xl);
    cudaGetSymbolAddress((void**)&oh, g_oh);
    cudaGetSymbolAddress((void**)&ol, g_ol);
    cudaGetSymbolAddress((void**)&wh, g_wh);
    cudaGetSymbolAddress((void**)&wl, g_wl);
    cudaGetSymbolAddress((void**)&qh, g_qh);
    cudaGetSymbolAddress((void**)&ql, g_ql);
    cudaGetSymbolAddress((void**)&kh, g_kh);
    cudaGetSymbolAddress((void**)&kl, g_kl);
    cudaGetSymbolAddress((void**)&vh, g_vh);
    cudaGetSymbolAddress((void**)&vl, g_vl);

    cudaFuncSetAttribute(gemm_hmma3, cudaFuncAttributeMaxDynamicSharedMemorySize, GEMM_SMEM);
    cudaFuncSetAttribute(attn_hmma,  cudaFuncAttributeMaxDynamicSharedMemorySize, ATT_SMEM);

    const int NX4 = BT * D / 4;
    const int NW4 = D * D / 4;

    split_kernel<<<NX4 / 256, 256>>>((const float4*)x, (ushort4*)xh, (ushort4*)xl, NX4);
    split_kernel<<<NW4 / 256, 256>>>((const float4*)Wq, (ushort4*)(wh + 0 * (size_t)D * D), (ushort4*)(wl + 0 * (size_t)D * D), NW4);
    split_kernel<<<NW4 / 256, 256>>>((const float4*)Wk, (ushort4*)(wh + 1 * (size_t)D * D), (ushort4*)(wl + 1 * (size_t)D * D), NW4);
    split_kernel<<<NW4 / 256, 256>>>((const float4*)Wv, (ushort4*)(wh + 2 * (size_t)D * D), (ushort4*)(wl + 2 * (size_t)D * D), NW4);
    split_kernel<<<NW4 / 256, 256>>>((const float4*)Wo, (ushort4*)(wh + 3 * (size_t)D * D), (ushort4*)(wl + 3 * (size_t)D * D), NW4);

    dim3 ggrid(D / 128, BT / 128);   // (16, 32)

    gemm_hmma3<<<ggrid, 256, GEMM_SMEM>>>(xh, xl, wh + 0 * (size_t)D * D, wl + 0 * (size_t)D * D, q_ptr, 1, TT, 0);
    gemm_hmma3<<<ggrid, 256, GEMM_SMEM>>>(xh, xl, wh + 1 * (size_t)D * D, wl + 1 * (size_t)D * D, new_k, 1, SK, 256);
    gemm_hmma3<<<ggrid, 256, GEMM_SMEM>>>(xh, xl, wh + 2 * (size_t)D * D, wl + 2 * (size_t)D * D, new_v, 1, SK, 256);

    prep_kernel<<<(NB * NH * SK * 32) / 256, 256>>>(past_k, past_v, new_k, new_v,
                                                    q_ptr, pos, qh, ql, kh, kl, vh, vl);

    attn_hmma<<<dim3(TT / 64, NB * NH), 128, ATT_SMEM>>>(qh, ql, kh, kl, vh, vl, oh, ol);

    gemm_hmma3<<<ggrid, 256, GEMM_SMEM>>>(oh, ol, wh + 3 * (size_t)D * D, wl + 3 * (size_t)D * D, out, 0, 0, 0);

    (void)in_sizes; (void)n_in; (void)out_size;
}

// round 16
// speedup vs baseline: 4.1269x; 1.4304x over previous
#include <cuda_runtime.h>
#include <cuda_bf16.h>
#include <cuda_fp16.h>
#include <cstdint>
#include <math.h>

#define D    2048
#define NH   32
#define HD   64
#define TT   256
#define NB   16
#define SK   512
#define BT   (NB*TT)   // 4096

#define OFF_K (BT*D)
#define NKV   (NB*NH*SK*HD)
#define OFF_V (OFF_K + NKV)

// ---------------- scratch (device globals; no allocation allowed) ----------
__device__ float g_q[NB*NH*TT*HD];     // Q proj (B,H,T,Hd) fp32 (pre-rope)

__device__ __half g_x16h[BT*D], g_x16l[BT*D];        // x split (fp16 hi/lo)
__device__ __half g_o16h[BT*D], g_o16l[BT*D];        // attention out split
__device__ __half g_w16[4*(size_t)D*D];              // Wq|Wk|Wv|Wo fp16

__device__ __nv_bfloat16 g_qh[NB*NH*TT*HD], g_ql[NB*NH*TT*HD]; // rope'd+scaled Q
__device__ __nv_bfloat16 g_kh[NKV], g_kl[NKV];       // attention K split
__device__ __nv_bfloat16 g_vh[NKV], g_vl[NKV];       // V split

// ---------------- helpers ---------------------------------------------------
__device__ __forceinline__ uint32_t smem_u32(const void* p) {
    uint32_t a;
    asm("{ .reg .u64 t; cvta.to.shared.u64 t, %1; cvt.u32.u64 %0, t; }" : "=r"(a) : "l"(p));
    return a;
}
__device__ __forceinline__ void cp16(uint32_t dst, const void* src) {
    asm volatile("cp.async.cg.shared.global [%0], [%1], 16;" :: "r"(dst), "l"(src));
}
#define CP_COMMIT() asm volatile("cp.async.commit_group;" ::: "memory")

__device__ __forceinline__ void ldm_x4(uint32_t* r, uint32_t addr) {
    asm volatile("ldmatrix.sync.aligned.m8n8.x4.shared.b16 {%0,%1,%2,%3}, [%4];"
        : "=r"(r[0]), "=r"(r[1]), "=r"(r[2]), "=r"(r[3]) : "r"(addr));
}
__device__ __forceinline__ void ldm_x4t(uint32_t* r, uint32_t addr) {
    asm volatile("ldmatrix.sync.aligned.m8n8.x4.trans.shared.b16 {%0,%1,%2,%3}, [%4];"
        : "=r"(r[0]), "=r"(r[1]), "=r"(r[2]), "=r"(r[3]) : "r"(addr));
}
__device__ __forceinline__ void mma_bf16(float* c, const uint32_t* a, const uint32_t* b) {
    asm volatile(
        "mma.sync.aligned.m16n8k16.row.col.f32.bf16.bf16.f32 "
        "{%0,%1,%2,%3}, {%4,%5,%6,%7}, {%8,%9}, {%0,%1,%2,%3};"
        : "+f"(c[0]), "+f"(c[1]), "+f"(c[2]), "+f"(c[3])
        : "r"(a[0]), "r"(a[1]), "r"(a[2]), "r"(a[3]), "r"(b[0]), "r"(b[1]));
}
__device__ __forceinline__ void mma_f16(float* c, const uint32_t* a, const uint32_t* b) {
    asm volatile(
        "mma.sync.aligned.m16n8k16.row.col.f32.f16.f16.f32 "
        "{%0,%1,%2,%3}, {%4,%5,%6,%7}, {%8,%9}, {%0,%1,%2,%3};"
        : "+f"(c[0]), "+f"(c[1]), "+f"(c[2]), "+f"(c[3])
        : "r"(a[0]), "r"(a[1]), "r"(a[2]), "r"(a[3]), "r"(b[0]), "r"(b[1]));
}
// pack two floats to bf16x2 / f16x2: 'lo' -> low half
__device__ __forceinline__ uint32_t pk(float lo, float hi) {
    uint32_t r;
    asm("cvt.rn.bf16x2.f32 %0, %1, %2;" : "=r"(r) : "f"(hi), "f"(lo));
    return r;
}
__device__ __forceinline__ uint32_t pkh(float lo, float hi) {
    uint32_t r;
    asm("cvt.rn.f16x2.f32 %0, %1, %2;" : "=r"(r) : "f"(hi), "f"(lo));
    return r;
}
__device__ __forceinline__ float bhi(float x) {
    __nv_bfloat16 h = __float2bfloat16(x);
    return __bfloat162float(h);
}
__device__ __forceinline__ float hhi(float x) {
    __half h = __float2half_rn(x);
    return __half2float(h);
}

// gemm smem tile: rows x 32 halfs (64B rows), xor swizzle
__device__ __forceinline__ uint32_t swoff(int r, int g) {
    return (uint32_t)(r * 64 + ((g ^ ((r >> 1) & 3)) * 16));
}
// attention smem tile: rows x 64 bf16 (128B rows), xor swizzle
__device__ __forceinline__ uint32_t vsw(int r, int g) {
    return (uint32_t)(r * 128 + ((g ^ (r & 7)) * 16));
}

#define TILE_B   8192                 // 128 x 64B
#define STAGE_B  (3 * TILE_B)         // Ah | Al | Bh
#define NSTAGE   3
#define GEMM_SMEM (NSTAGE * STAGE_B)  // 73728

#define ATT_STAGE 32768               // Kh | Kl | Vh | Vl (8KB each)
#define ATT_SMEM  (32768 + 3 * ATT_STAGE)   // Qh,Ql (32KB) + 3 KV stages = 131072

// ---------------- splits ----------------------------------------------------
__global__ void split_hl16(const float4* __restrict__ src,
                           ushort4* __restrict__ hi, ushort4* __restrict__ lo, int n4)
{
    int i = blockIdx.x * blockDim.x + threadIdx.x;
    if (i >= n4) return;
    float4 v = src[i];
    float f[4] = {v.x, v.y, v.z, v.w};
    unsigned short h[4], l[4];
    #pragma unroll
    for (int j = 0; j < 4; ++j) {
        __half hb = __float2half_rn(f[j]);
        float hf = __half2float(hb);
        __half lb = __float2half_rn(f[j] - hf);
        h[j] = *reinterpret_cast<unsigned short*>(&hb);
        l[j] = *reinterpret_cast<unsigned short*>(&lb);
    }
    hi[i] = make_ushort4(h[0], h[1], h[2], h[3]);
    lo[i] = make_ushort4(l[0], l[1], l[2], l[3]);
}

__global__ void split_h16(const float4* __restrict__ src,
                          ushort4* __restrict__ hi, int n4)
{
    int i = blockIdx.x * blockDim.x + threadIdx.x;
    if (i >= n4) return;
    float4 v = src[i];
    float f[4] = {v.x, v.y, v.z, v.w};
    unsigned short h[4];
    #pragma unroll
    for (int j = 0; j < 4; ++j) {
        __half hb = __float2half_rn(f[j]);
        h[j] = *reinterpret_cast<unsigned short*>(&hb);
    }
    hi[i] = make_ushort4(h[0], h[1], h[2], h[3]);
}

// ---------------- fp16 2-term GEMM: C = (Ah+Al) @ Bh^T ----------------------
// fused=1: B spans 3*D rows (Wq|Wk|Wv); scatter per proj to Cq/Ck/Cv (B,H,S,Hd)
// fused=0: B spans D rows; C row-major into Cq, ldc = D
__global__ __launch_bounds__(256, 2)
void gemm_f16x2(const __half* __restrict__ Ah, const __half* __restrict__ Al,
                const __half* __restrict__ Bh,
                float* __restrict__ Cq, float* __restrict__ Ck, float* __restrict__ Cv,
                int fused)
{
    extern __shared__ char smem[];
    const uint32_t sbase = smem_u32(smem);

    const int tid  = threadIdx.x;
    const int wid  = tid >> 5;
    const int lane = tid & 31;
    const int wm   = wid & 3;
    const int wn   = wid >> 2;

    const int m0 = blockIdx.y * 128;
    const int n0 = blockIdx.x * 128;

    int r0 = tid >> 2, g0 = tid & 3;
    int r1 = r0 + 64;
    const uint32_t so0 = swoff(r0, g0);
    const uint32_t so1 = swoff(r1, g0);
    const __half* a0h = Ah + (size_t)(m0 + r0) * D + g0 * 8;
    const __half* a0l = Al + (size_t)(m0 + r0) * D + g0 * 8;
    const __half* b0h = Bh + (size_t)(n0 + r0) * D + g0 * 8;
    const __half* a1h = Ah + (size_t)(m0 + r1) * D + g0 * 8;
    const __half* a1l = Al + (size_t)(m0 + r1) * D + g0 * 8;
    const __half* b1h = Bh + (size_t)(n0 + r1) * D + g0 * 8;

    uint32_t aoff[2][2], boff[4][2];
    #pragma unroll
    for (int mt = 0; mt < 2; ++mt) {
        int row = wm * 32 + mt * 16 + (lane & 15);
        #pragma unroll
        for (int ks = 0; ks < 2; ++ks)
            aoff[mt][ks] = swoff(row, ks * 2 + (lane >> 4));
    }
    #pragma unroll
    for (int np = 0; np < 4; ++np) {
        int nr = wn * 64 + np * 16 + (lane & 7) + ((lane >> 4) << 3);
        #pragma unroll
        for (int ks = 0; ks < 2; ++ks)
            boff[np][ks] = swoff(nr, ks * 2 + ((lane >> 3) & 1));
    }

    float acc[2][8][4];
    #pragma unroll
    for (int mt = 0; mt < 2; ++mt)
        #pragma unroll
        for (int nt = 0; nt < 8; ++nt)
            #pragma unroll
            for (int v = 0; v < 4; ++v) acc[mt][nt][v] = 0.f;

    const int nchunk = D / 32;   // 64

    #pragma unroll
    for (int s = 0; s < NSTAGE - 1; ++s) {
        uint32_t sb = sbase + s * STAGE_B;
        int ko = s * 32;
        cp16(sb + 0*TILE_B + so0, a0h + ko); cp16(sb + 0*TILE_B + so1, a1h + ko);
        cp16(sb + 1*TILE_B + so0, a0l + ko); cp16(sb + 1*TILE_B + so1, a1l + ko);
        cp16(sb + 2*TILE_B + so0, b0h + ko); cp16(sb + 2*TILE_B + so1, b1h + ko);
        CP_COMMIT();
    }

    for (int kc = 0; kc < nchunk; ++kc) {
        if (kc + 1 < nchunk) asm volatile("cp.async.wait_group 1;" ::: "memory");
        else                 asm volatile("cp.async.wait_group 0;" ::: "memory");
        __syncthreads();

        if (kc + NSTAGE - 1 < nchunk) {
            uint32_t sb = sbase + ((kc + NSTAGE - 1) % NSTAGE) * STAGE_B;
            int ko = (kc + NSTAGE - 1) * 32;
            cp16(sb + 0*TILE_B + so0, a0h + ko); cp16(sb + 0*TILE_B + so1, a1h + ko);
            cp16(sb + 1*TILE_B + so0, a0l + ko); cp16(sb + 1*TILE_B + so1, a1l + ko);
            cp16(sb + 2*TILE_B + so0, b0h + ko); cp16(sb + 2*TILE_B + so1, b1h + ko);
            CP_COMMIT();
        }

        const uint32_t sb = sbase + (kc % NSTAGE) * STAGE_B;
        #pragma unroll
        for (int ks = 0; ks < 2; ++ks) {
            uint32_t ah[2][4], al[2][4];
            ldm_x4(ah[0], sb + 0*TILE_B + aoff[0][ks]);
            ldm_x4(ah[1], sb + 0*TILE_B + aoff[1][ks]);
            ldm_x4(al[0], sb + 1*TILE_B + aoff[0][ks]);
            ldm_x4(al[1], sb + 1*TILE_B + aoff[1][ks]);
            #pragma unroll
            for (int np = 0; np < 4; ++np) {
                uint32_t bq[4];
                ldm_x4(bq, sb + 2*TILE_B + boff[np][ks]);
                #pragma unroll
                for (int mt = 0; mt < 2; ++mt) {
                    mma_f16(acc[mt][np*2+0], ah[mt], bq + 0);
                    mma_f16(acc[mt][np*2+1], ah[mt], bq + 2);
                    mma_f16(acc[mt][np*2+0], al[mt], bq + 0);
                    mma_f16(acc[mt][np*2+1], al[mt], bq + 2);
                }
            }
        }
    }

    const int er = lane >> 2;
    const int ec = (lane & 3) * 2;
    #pragma unroll
    for (int mt = 0; mt < 2; ++mt) {
        #pragma unroll
        for (int nt = 0; nt < 8; ++nt) {
            int gm = m0 + wm * 32 + mt * 16 + er;
            int gc = n0 + wn * 64 + nt * 8 + ec;
            if (!fused) {
                float* dst = Cq + (size_t)gm * D + gc;
                *(float2*)dst = make_float2(acc[mt][nt][0], acc[mt][nt][1]);
                *(float2*)(dst + 8 * D) = make_float2(acc[mt][nt][2], acc[mt][nt][3]);
            } else {
                int proj = gc >> 11;
                int nl = gc & 2047;
                int h = nl >> 6, d = nl & 63;
                int b = gm >> 8, t = gm & 255;
                float* Cb = (proj == 0) ? Cq : ((proj == 1) ? Ck : Cv);
                int S  = (proj == 0) ? TT : SK;
                int s0 = (proj == 0) ? 0 : 256;
                float* dst = Cb + ((size_t)((b * NH + h) * S + s0 + t)) * HD + d;
                *(float2*)dst = make_float2(acc[mt][nt][0], acc[mt][nt][1]);
                float* dst2 = Cb + ((size_t)((b * NH + h) * S + s0 + t + 8)) * HD + d;
                *(float2*)dst2 = make_float2(acc[mt][nt][2], acc[mt][nt][3]);
            }
        }
    }
}

// ---------------- prep: cache tail copies + RoPE + bf16 splits --------------
__global__ void prep_kernel(const float* __restrict__ past_k,
                            const float* __restrict__ past_v,
                            float* __restrict__ new_k,
                            float* __restrict__ new_v,
                            const float* __restrict__ q,
                            const int* __restrict__ pos_ptr,
                            __nv_bfloat16* __restrict__ qh, __nv_bfloat16* __restrict__ ql,
                            __nv_bfloat16* __restrict__ kh, __nv_bfloat16* __restrict__ kl,
                            __nv_bfloat16* __restrict__ vh, __nv_bfloat16* __restrict__ vl)
{
    int idx = blockIdx.x * blockDim.x + threadIdx.x;
    int j  = idx & 31;
    int s  = (idx >> 5) & 511;
    int bh = idx >> 14;

    size_t dk = ((size_t)bh * SK + s) * HD + j * 2;

    if (s < 256) {
        size_t src = ((size_t)bh * SK + (s + 256)) * HD + j * 2;
        float2 kp = *(const float2*)(past_k + src);
        float2 vp = *(const float2*)(past_v + src);
        *(float2*)(new_k + dk) = kp;
        *(float2*)(new_v + dk) = vp;
        float kh0 = bhi(kp.x), kh1 = bhi(kp.y);
        *(uint32_t*)(kh + dk) = pk(kh0, kh1);
        *(uint32_t*)(kl + dk) = pk(kp.x - kh0, kp.y - kh1);
        float vh0 = bhi(vp.x), vh1 = bhi(vp.y);
        *(uint32_t*)(vh + dk) = pk(vh0, vh1);
        *(uint32_t*)(vl + dk) = pk(vp.x - vh0, vp.y - vh1);
    } else {
        int t = s - 256;
        float pos = (float)(pos_ptr[0] + t);
        float inv = exp2f(-(float)j * 0.41524101186091403f);
        float ang = pos * inv;
        float sn, cs;
        sincosf(ang, &sn, &cs);

        float2 kv = *(const float2*)(new_k + dk);
        float2 kr = {kv.x * cs - kv.y * sn, kv.x * sn + kv.y * cs};
        float kh0 = bhi(kr.x), kh1 = bhi(kr.y);
        *(uint32_t*)(kh + dk) = pk(kh0, kh1);
        *(uint32_t*)(kl + dk) = pk(kr.x - kh0, kr.y - kh1);

        float2 vp = *(const float2*)(new_v + dk);
        float vh0 = bhi(vp.x), vh1 = bhi(vp.y);
        *(uint32_t*)(vh + dk) = pk(vh0, vh1);
        *(uint32_t*)(vl + dk) = pk(vp.x - vh0, vp.y - vh1);

        size_t dq = ((size_t)bh * TT + t) * HD + j * 2;
        float2 qv = *(const float2*)(q + dq);
        float2 qr = {(qv.x * cs - qv.y * sn) * 0.125f, (qv.x * sn + qv.y * cs) * 0.125f};
        float qh0 = bhi(qr.x), qh1 = bhi(qr.y);
        *(uint32_t*)(qh + dq) = pk(qh0, qh1);
        *(uint32_t*)(ql + dq) = pk(qr.x - qh0, qr.y - qh1);
    }
}

// ---------------- attention: HMMA flash, 128 q (8 warps) x 64-key chunks ----
__global__ __launch_bounds__(256)
void attn_hmma(const __nv_bfloat16* __restrict__ Qh, const __nv_bfloat16* __restrict__ Ql,
               const __nv_bfloat16* __restrict__ Kh, const __nv_bfloat16* __restrict__ Kl,
               const __nv_bfloat16* __restrict__ Vh, const __nv_bfloat16* __restrict__ Vl,
               __half* __restrict__ Oh, __half* __restrict__ Ol)
{
    extern __shared__ char sm[];
    const uint32_t sb = smem_u32(sm);
    const int tid = threadIdx.x, wid = tid >> 5, lane = tid & 31;
    const int bh = blockIdx.y, q0 = blockIdx.x * 128;

    const __nv_bfloat16* Qhg = Qh + ((size_t)bh * TT + q0) * HD;
    const __nv_bfloat16* Qlg = Ql + ((size_t)bh * TT + q0) * HD;
    const __nv_bfloat16* Khg = Kh + (size_t)bh * SK * HD;
    const __nv_bfloat16* Klg = Kl + (size_t)bh * SK * HD;
    const __nv_bfloat16* Vhg = Vh + (size_t)bh * SK * HD;
    const __nv_bfloat16* Vlg = Vl + (size_t)bh * SK * HD;

    // Q tiles: Qh at +0 (16KB), Ql at +16384
    #pragma unroll
    for (int i = 0; i < 4; ++i) {
        int u = i * 256 + tid, r = u >> 3, g = u & 7;
        uint32_t off = vsw(r, g);
        cp16(sb + off,         Qhg + r * HD + g * 8);
        cp16(sb + 16384 + off, Qlg + r * HD + g * 8);
    }
    CP_COMMIT();

    const int nchunk = (q0 + 384) >> 6;   // 6 or 8

    // chunk 0
    {
        uint32_t st = sb + 32768;
        #pragma unroll
        for (int i = 0; i < 2; ++i) {
            int u = i * 256 + tid, r = u >> 3, g = u & 7;
            uint32_t off = vsw(r, g);
            int go = r * HD + g * 8;
            cp16(st + off,         Khg + go);
            cp16(st + 8192 + off,  Klg + go);
            cp16(st + 16384 + off, Vhg + go);
            cp16(st + 24576 + off, Vlg + go);
        }
        CP_COMMIT();
    }

    float m0r = -1e30f, m1r = -1e30f, l0 = 0.f, l1 = 0.f;
    float oacc[8][4];
    #pragma unroll
    for (int f = 0; f < 8; ++f)
        #pragma unroll
        for (int v = 0; v < 4; ++v) oacc[f][v] = 0.f;

    const int arow  = (wid << 4) + (lane & 15);
    const int acolb = lane >> 4;
    const int brow  = (lane & 7) + ((lane >> 4) << 3);
    const int bcol  = (lane >> 3) & 1;
    const int vrow  = (((lane >> 3) & 1) << 3) + (lane & 7);
    const int vcolb = lane >> 4;
    const int t0    = q0 + (wid << 4) + (lane >> 2);

    for (int c = 0; c < nchunk; ++c) {
        if (c + 1 < nchunk) {
            uint32_t st = sb + 32768 + ((c + 1) % 3) * ATT_STAGE;
            int s0 = (c + 1) * 64;
            #pragma unroll
            for (int i = 0; i < 2; ++i) {
                int u = i * 256 + tid, r = u >> 3, g = u & 7;
                uint32_t off = vsw(r, g);
                int go = (s0 + r) * HD + g * 8;
                cp16(st + off,         Khg + go);
                cp16(st + 8192 + off,  Klg + go);
                cp16(st + 16384 + off, Vhg + go);
                cp16(st + 24576 + off, Vlg + go);
            }
            CP_COMMIT();
            asm volatile("cp.async.wait_group 1;" ::: "memory");
        } else {
            asm volatile("cp.async.wait_group 0;" ::: "memory");
        }
        __syncthreads();

        const uint32_t kb = sb + 32768 + (c % 3) * ATT_STAGE;

        // ---- S = Q K^T (3-term bf16) ----
        float sacc[8][4];
        #pragma unroll
        for (int f = 0; f < 8; ++f)
            #pragma unroll
            for (int v = 0; v < 4; ++v) sacc[f][v] = 0.f;

        #pragma unroll
        for (int ks = 0; ks < 4; ++ks) {
            uint32_t aQh[4], aQl[4];
            ldm_x4(aQh, sb + vsw(arow, ks * 2 + acolb));
            ldm_x4(aQl, sb + 16384 + vsw(arow, ks * 2 + acolb));
            #pragma unroll
            for (int p = 0; p < 4; ++p) {
                uint32_t bk[4];
                ldm_x4(bk, kb + vsw(p * 16 + brow, ks * 2 + bcol));
                mma_bf16(sacc[2*p],   aQh, bk + 0);
                mma_bf16(sacc[2*p+1], aQh, bk + 2);
                mma_bf16(sacc[2*p],   aQl, bk + 0);
                mma_bf16(sacc[2*p+1], aQl, bk + 2);
                ldm_x4(bk, kb + 8192 + vsw(p * 16 + brow, ks * 2 + bcol));
                mma_bf16(sacc[2*p],   aQh, bk + 0);
                mma_bf16(sacc[2*p+1], aQh, bk + 2);
            }
        }

        // ---- mask ----
        if (c * 64 + 63 > q0 + (wid << 4) + 256) {
            #pragma unroll
            for (int f = 0; f < 8; ++f) {
                int s = c * 64 + f * 8 + ((lane & 3) << 1);
                if (s     > t0 + 256) sacc[f][0] = -1e30f;
                if (s + 1 > t0 + 256) sacc[f][1] = -1e30f;
                if (s     > t0 + 264) sacc[f][2] = -1e30f;
                if (s + 1 > t0 + 264) sacc[f][3] = -1e30f;
            }
        }

        // ---- online softmax ----
        float mx0 = -1e30f, mx1 = -1e30f;
        #pragma unroll
        for (int f = 0; f < 8; ++f) {
            mx0 = fmaxf(mx0, fmaxf(sacc[f][0], sacc[f][1]));
            mx1 = fmaxf(mx1, fmaxf(sacc[f][2], sacc[f][3]));
        }
        mx0 = fmaxf(mx0, __shfl_xor_sync(0xffffffffu, mx0, 1));
        mx0 = fmaxf(mx0, __shfl_xor_sync(0xffffffffu, mx0, 2));
        mx1 = fmaxf(mx1, __shfl_xor_sync(0xffffffffu, mx1, 1));
        mx1 = fmaxf(mx1, __shfl_xor_sync(0xffffffffu, mx1, 2));

        float mn0 = fmaxf(m0r, mx0), mn1 = fmaxf(m1r, mx1);
        float e0 = __expf(m0r - mn0), e1 = __expf(m1r - mn1);
        m0r = mn0; m1r = mn1;

        float rs0 = 0.f, rs1 = 0.f;
        #pragma unroll
        for (int f = 0; f < 8; ++f) {
            float p0 = __expf(sacc[f][0] - mn0); sacc[f][0] = p0; rs0 += p0;
            float p1 = __expf(sacc[f][1] - mn0); sacc[f][1] = p1; rs0 += p1;
            float p2 = __expf(sacc[f][2] - mn1); sacc[f][2] = p2; rs1 += p2;
            float p3 = __expf(sacc[f][3] - mn1); sacc[f][3] = p3; rs1 += p3;
        }
        rs0 += __shfl_xor_sync(0xffffffffu, rs0, 1);
        rs0 += __shfl_xor_sync(0xffffffffu, rs0, 2);
        rs1 += __shfl_xor_sync(0xffffffffu, rs1, 1);
        rs1 += __shfl_xor_sync(0xffffffffu, rs1, 2);
        l0 = l0 * e0 + rs0;
        l1 = l1 * e1 + rs1;

        #pragma unroll
        for (int f = 0; f < 8; ++f) {
            oacc[f][0] *= e0; oacc[f][1] *= e0;
            oacc[f][2] *= e1; oacc[f][3] *= e1;
        }

        // ---- O += P V (3-term bf16, P from registers) ----
        #pragma unroll
        for (int ks = 0; ks < 4; ++ks) {
            const int f0 = 2 * ks, f1 = 2 * ks + 1;
            float h00 = bhi(sacc[f0][0]), h01 = bhi(sacc[f0][1]);
            float h02 = bhi(sacc[f0][2]), h03 = bhi(sacc[f0][3]);
            float h10 = bhi(sacc[f1][0]), h11 = bhi(sacc[f1][1]);
            float h12 = bhi(sacc[f1][2]), h13 = bhi(sacc[f1][3]);
            uint32_t pha[4] = { pk(h00, h01), pk(h02, h03), pk(h10, h11), pk(h12, h13) };
            uint32_t pla[4] = { pk(sacc[f0][0]-h00, sacc[f0][1]-h01),
                                pk(sacc[f0][2]-h02, sacc[f0][3]-h03),
                                pk(sacc[f1][0]-h10, sacc[f1][1]-h11),
                                pk(sacc[f1][2]-h12, sacc[f1][3]-h13) };
            #pragma unroll
            for (int p = 0; p < 4; ++p) {
                uint32_t bv[4];
                ldm_x4t(bv, kb + 16384 + vsw(ks * 16 + vrow, p * 2 + vcolb));
                mma_bf16(oacc[2*p],   pha, bv + 0);
                mma_bf16(oacc[2*p+1], pha, bv + 2);
                mma_bf16(oacc[2*p],   pla, bv + 0);
                mma_bf16(oacc[2*p+1], pla, bv + 2);
                ldm_x4t(bv, kb + 24576 + vsw(ks * 16 + vrow, p * 2 + vcolb));
                mma_bf16(oacc[2*p],   pha, bv + 0);
                mma_bf16(oacc[2*p+1], pha, bv + 2);
            }
        }
    }

    // ---- epilogue: write fp16 hi/lo split of O in (B,T,D) ----
    const float inv0 = 1.f / l0, inv1 = 1.f / l1;
    const int b = bh >> 5, h = bh & 31;
    const int d0 = h * 64 + ((lane & 3) << 1);
    #pragma unroll
    for (int f = 0; f < 8; ++f) {
        size_t i0 = ((size_t)(b * TT + t0)) * D + d0 + f * 8;
        size_t i1 = ((size_t)(b * TT + t0 + 8)) * D + d0 + f * 8;
        float v0 = oacc[f][0] * inv0, v1 = oacc[f][1] * inv0;
        float v2 = oacc[f][2] * inv1, v3 = oacc[f][3] * inv1;
        float a0 = hhi(v0), a1 = hhi(v1), a2 = hhi(v2), a3 = hhi(v3);
        *(uint32_t*)(Oh + i0) = pkh(a0, a1);
        *(uint32_t*)(Ol + i0) = pkh(v0 - a0, v1 - a1);
        *(uint32_t*)(Oh + i1) = pkh(a2, a3);
        *(uint32_t*)(Ol + i1) = pkh(v2 - a2, v3 - a3);
    }
}

// ---------------- launch ----------------------------------------------------
extern "C" void kernel_launch(void* const* d_in, const int* in_sizes, int n_in,
                              void* d_out, int out_size)
{
    const float* x      = (const float*)d_in[0];
    const float* past_k = (const float*)d_in[1];
    const float* past_v = (const float*)d_in[2];
    const float* Wq     = (const float*)d_in[3];
    const float* Wk     = (const float*)d_in[4];
    const float* Wv     = (const float*)d_in[5];
    const float* Wo     = (const float*)d_in[6];
    const int*   pos    = (const int*)d_in[7];

    float* out   = (float*)d_out;
    float* new_k = out + OFF_K;
    float* new_v = out + OFF_V;

    float* q_ptr;
    __half *x16h, *x16l, *o16h, *o16l, *w16;
    __nv_bfloat16 *qh, *ql, *kh, *kl, *vh, *vl;
    cudaGetSymbolAddress((void**)&q_ptr, g_q);
    cudaGetSymbolAddress((void**)&x16h, g_x16h);
    cudaGetSymbolAddress((void**)&x16l, g_x16l);
    cudaGetSymbolAddress((void**)&o16h, g_o16h);
    cudaGetSymbolAddress((void**)&o16l, g_o16l);
    cudaGetSymbolAddress((void**)&w16,  g_w16);
    cudaGetSymbolAddress((void**)&qh, g_qh);
    cudaGetSymbolAddress((void**)&ql, g_ql);
    cudaGetSymbolAddress((void**)&kh, g_kh);
    cudaGetSymbolAddress((void**)&kl, g_kl);
    cudaGetSymbolAddress((void**)&vh, g_vh);
    cudaGetSymbolAddress((void**)&vl, g_vl);

    cudaFuncSetAttribute(gemm_f16x2, cudaFuncAttributeMaxDynamicSharedMemorySize, GEMM_SMEM);
    cudaFuncSetAttribute(attn_hmma,  cudaFuncAttributeMaxDynamicSharedMemorySize, ATT_SMEM);

    const int NX4 = BT * D / 4;
    const int NW4 = D * D / 4;

    // splits: x -> fp16 hi/lo; weights -> fp16 single (Wq|Wk|Wv|Wo contiguous)
    split_hl16<<<NX4 / 256, 256>>>((const float4*)x, (ushort4*)x16h, (ushort4*)x16l, NX4);
    split_h16<<<NW4 / 256, 256>>>((const float4*)Wq, (ushort4*)(w16 + 0 * (size_t)D * D), NW4);
    split_h16<<<NW4 / 256, 256>>>((const float4*)Wk, (ushort4*)(w16 + 1 * (size_t)D * D), NW4);
    split_h16<<<NW4 / 256, 256>>>((const float4*)Wv, (ushort4*)(w16 + 2 * (size_t)D * D), NW4);
    split_h16<<<NW4 / 256, 256>>>((const float4*)Wo, (ushort4*)(w16 + 3 * (size_t)D * D), NW4);

    // fused Q/K/V projection (B rows span 3*D)
    gemm_f16x2<<<dim3(3 * D / 128, BT / 128), 256, GEMM_SMEM>>>(
        x16h, x16l, w16, q_ptr, new_k, new_v, 1);

    // cache-tail copies + RoPE + attention splits
    prep_kernel<<<(NB * NH * SK * 32) / 256, 256>>>(past_k, past_v, new_k, new_v,
                                                    q_ptr, pos, qh, ql, kh, kl, vh, vl);

    // attention (128 queries x 8 warps per CTA)
    attn_hmma<<<dim3(TT / 128, NB * NH), 256, ATT_SMEM>>>(qh, ql, kh, kl, vh, vl, o16h, o16l);

    // O projection
    gemm_f16x2<<<dim3(D / 128, BT / 128), 256, GEMM_SMEM>>>(
        o16h, o16l, w16 + 3 * (size_t)D * D, out, nullptr, nullptr, 0);

    (void)in_sizes; (void)n_in; (void)out_size;
}